// round 1
// baseline (speedup 1.0000x reference)
#include <cuda_runtime.h>

#define FDIM 128
#define HID 64
#define MS 64
#define HH 56
#define WW 56
#define BATCH 8
#define PIX (HH*WW)   // 3136

// Scratch: features transposed to (b, y, x, c) so bilinear corners are contiguous 512B.
__device__ float g_feat[BATCH * PIX * FDIM];

// ---------------- transpose kernel: (B,C,H,W) -> (B,H*W,C) ----------------
__global__ __launch_bounds__(256) void transpose_kernel(const float* __restrict__ feat) {
    int blk = blockIdx.x;            // 8 * 98 blocks
    int b = blk / 98;
    int pix0 = (blk % 98) * 32;
    __shared__ float tile[FDIM][33]; // padded, conflict-free
    int tx = threadIdx.x & 31;
    int ty = threadIdx.x >> 5;       // 0..7
    const float* src = feat + (size_t)b * FDIM * PIX;
    #pragma unroll
    for (int k = 0; k < 16; k++) {
        int c = ty + (k << 3);
        tile[c][tx] = src[c * PIX + pix0 + tx];   // coalesced read
    }
    __syncthreads();
    int c2 = threadIdx.x & 127;
    int pg = threadIdx.x >> 7;       // 0..1
    float* dst = g_feat + ((size_t)b * PIX + pix0) * FDIM;
    #pragma unroll
    for (int p = pg; p < 32; p += 2) {
        dst[p * FDIM + c2] = tile[c2][p];          // coalesced write
    }
}

// ---------------- fused decoder kernel ----------------
// 256 threads per CTA, one point per thread.
// Shared: W1(16384) W2(4096) W3(4096) W4(64) b1,b2,b3(64 each) Bg(192) + sH(64*256)
#define SM_W1   0
#define SM_W2   16384
#define SM_W3   (16384+4096)
#define SM_W4   (16384+4096+4096)
#define SM_B1   (SM_W4+64)
#define SM_B2   (SM_B1+64)
#define SM_B3   (SM_B2+64)
#define SM_BG   (SM_B3+64)
#define SM_H    (SM_BG+192)
#define SM_FLOATS (SM_H + 64*256)

__global__ __launch_bounds__(256, 1) void decoder_kernel(
    const float* __restrict__ points, const float* __restrict__ kmat,
    const float* __restrict__ rtm, const float* __restrict__ Bg,
    const float* __restrict__ W1, const float* __restrict__ b1,
    const float* __restrict__ W2, const float* __restrict__ b2,
    const float* __restrict__ W3, const float* __restrict__ b3,
    const float* __restrict__ W4, const float* __restrict__ b4,
    float* __restrict__ out)
{
    extern __shared__ float sm[];
    float* sW1 = sm + SM_W1;
    float* sW2 = sm + SM_W2;
    float* sW3 = sm + SM_W3;
    float* sW4 = sm + SM_W4;
    float* sb1 = sm + SM_B1;
    float* sb2 = sm + SM_B2;
    float* sb3 = sm + SM_B3;
    float* sBg = sm + SM_BG;
    float* sH  = sm + SM_H;

    int tid = threadIdx.x;
    for (int i = tid; i < 16384; i += 256) sW1[i] = W1[i];
    for (int i = tid; i < 4096; i += 256) { sW2[i] = W2[i]; sW3[i] = W3[i]; }
    if (tid < 64) { sW4[tid]=W4[tid]; sb1[tid]=b1[tid]; sb2[tid]=b2[tid]; sb3[tid]=b3[tid]; }
    if (tid < 192) sBg[tid] = Bg[tid];
    __syncthreads();

    int pid = blockIdx.x * 256 + tid;
    int b = pid >> 16;

    // ---- projection ----
    const float* rtb = rtm + b * 12;
    const float* kb  = kmat + b * 9;
    float px = points[pid*3+0];
    float py = points[pid*3+1];
    float pz = points[pid*3+2];
    float cx = rtb[0]*px + rtb[1]*py + rtb[2]*pz + rtb[3];
    float cy = rtb[4]*px + rtb[5]*py + rtb[6]*pz + rtb[7];
    float cz = rtb[8]*px + rtb[9]*py + rtb[10]*pz + rtb[11];
    float ix = kb[0]*cx + kb[1]*cy + kb[2]*cz;
    float iy = kb[3]*cx + kb[4]*cy + kb[5]*cz;
    float iz = kb[6]*cx + kb[7]*cy + kb[8]*cz;
    float zd = iz + 1e-8f;
    float u = ix / zd;
    float v = iy / zd;
    float valid = (iz > 0.f) ? 1.f : 0.f;
    float un = (2.f*u + 1.f) / (float)WW - 1.f;
    float vn = (2.f*v + 1.f) / (float)HH - 1.f;
    float xs = ((un + 1.f) * (float)WW - 1.f) * 0.5f;
    float ys = ((vn + 1.f) * (float)HH - 1.f) * 0.5f;

    float x0f = floorf(xs), y0f = floorf(ys);
    float fx = xs - x0f, fy = ys - y0f;
    int x0 = (int)x0f, y0 = (int)y0f;
    int x1 = x0 + 1, y1 = y0 + 1;
    float w00 = (1.f-fx)*(1.f-fy);
    float w01 = fx*(1.f-fy);
    float w10 = (1.f-fx)*fy;
    float w11 = fx*fy;
    w00 *= ((x0>=0 && x0<WW && y0>=0 && y0<HH) ? valid : 0.f);
    w01 *= ((x1>=0 && x1<WW && y0>=0 && y0<HH) ? valid : 0.f);
    w10 *= ((x0>=0 && x0<WW && y1>=0 && y1<HH) ? valid : 0.f);
    w11 *= ((x1>=0 && x1<WW && y1>=0 && y1<HH) ? valid : 0.f);
    int x0c = min(max(x0,0),WW-1), x1c = min(max(x1,0),WW-1);
    int y0c = min(max(y0,0),HH-1), y1c = min(max(y1,0),HH-1);
    const float4* p00 = (const float4*)(g_feat + (((size_t)b*HH + y0c)*WW + x0c)*FDIM);
    const float4* p01 = (const float4*)(g_feat + (((size_t)b*HH + y0c)*WW + x1c)*FDIM);
    const float4* p10 = (const float4*)(g_feat + (((size_t)b*HH + y1c)*WW + x0c)*FDIM);
    const float4* p11 = (const float4*)(g_feat + (((size_t)b*HH + y1c)*WW + x1c)*FDIM);

    // ---- layer 1 accumulators ----
    float acc[64];
    #pragma unroll
    for (int j = 0; j < 64; j++) acc[j] = sb1[j];

    // image feature part (inputs 0..127), streamed 4 channels at a time
    #pragma unroll 2
    for (int c4 = 0; c4 < 32; c4++) {
        float4 a = p00[c4];
        float4 bb = p01[c4];
        float4 cc = p10[c4];
        float4 dd = p11[c4];
        float f0 = w00*a.x + w01*bb.x + w10*cc.x + w11*dd.x;
        float f1 = w00*a.y + w01*bb.y + w10*cc.y + w11*dd.y;
        float f2 = w00*a.z + w01*bb.z + w10*cc.z + w11*dd.z;
        float f3 = w00*a.w + w01*bb.w + w10*cc.w + w11*dd.w;
        const float4* r0 = (const float4*)(sW1 + (c4*4+0)*64);
        const float4* r1 = (const float4*)(sW1 + (c4*4+1)*64);
        const float4* r2 = (const float4*)(sW1 + (c4*4+2)*64);
        const float4* r3 = (const float4*)(sW1 + (c4*4+3)*64);
        #pragma unroll
        for (int jj = 0; jj < 16; jj++) {
            float4 q0 = r0[jj], q1 = r1[jj], q2 = r2[jj], q3 = r3[jj];
            acc[4*jj+0] += f0*q0.x + f1*q1.x + f2*q2.x + f3*q3.x;
            acc[4*jj+1] += f0*q0.y + f1*q1.y + f2*q2.y + f3*q3.y;
            acc[4*jj+2] += f0*q0.z + f1*q1.z + f2*q2.z + f3*q3.z;
            acc[4*jj+3] += f0*q0.w + f1*q1.w + f2*q2.w + f3*q3.w;
        }
    }

    // Fourier part (inputs 128..255): sin row (128+m), cos row (192+m)
    const float TWO_PI = 6.283185307179586f;
    #pragma unroll 2
    for (int m = 0; m < 64; m++) {
        float ang = TWO_PI * (px*sBg[3*m+0] + py*sBg[3*m+1] + pz*sBg[3*m+2]);
        float sv, cv;
        __sincosf(ang, &sv, &cv);
        const float4* rs = (const float4*)(sW1 + (128+m)*64);
        const float4* rc = (const float4*)(sW1 + (192+m)*64);
        #pragma unroll
        for (int jj = 0; jj < 16; jj++) {
            float4 qs = rs[jj], qc = rc[jj];
            acc[4*jj+0] += sv*qs.x + cv*qc.x;
            acc[4*jj+1] += sv*qs.y + cv*qc.y;
            acc[4*jj+2] += sv*qs.z + cv*qc.z;
            acc[4*jj+3] += sv*qs.w + cv*qc.w;
        }
    }

    // relu -> shared (private column per thread, no sync needed)
    #pragma unroll
    for (int j = 0; j < 64; j++) sH[j*256 + tid] = fmaxf(acc[j], 0.f);

    // ---- layer 2 ----
    #pragma unroll
    for (int j = 0; j < 64; j++) acc[j] = sb2[j];
    #pragma unroll 4
    for (int i = 0; i < 64; i++) {
        float hv = sH[i*256 + tid];
        const float4* r = (const float4*)(sW2 + i*64);
        #pragma unroll
        for (int jj = 0; jj < 16; jj++) {
            float4 w = r[jj];
            acc[4*jj+0] += hv*w.x;
            acc[4*jj+1] += hv*w.y;
            acc[4*jj+2] += hv*w.z;
            acc[4*jj+3] += hv*w.w;
        }
    }
    #pragma unroll
    for (int j = 0; j < 64; j++) sH[j*256 + tid] = fmaxf(acc[j], 0.f);

    // ---- layer 3 ----
    #pragma unroll
    for (int j = 0; j < 64; j++) acc[j] = sb3[j];
    #pragma unroll 4
    for (int i = 0; i < 64; i++) {
        float hv = sH[i*256 + tid];
        const float4* r = (const float4*)(sW3 + i*64);
        #pragma unroll
        for (int jj = 0; jj < 16; jj++) {
            float4 w = r[jj];
            acc[4*jj+0] += hv*w.x;
            acc[4*jj+1] += hv*w.y;
            acc[4*jj+2] += hv*w.z;
            acc[4*jj+3] += hv*w.w;
        }
    }

    // ---- layer 4 ----
    float o = b4[0];
    #pragma unroll
    for (int j = 0; j < 64; j++) o += fmaxf(acc[j], 0.f) * sW4[j];
    out[pid] = o;
}

extern "C" void kernel_launch(void* const* d_in, const int* in_sizes, int n_in,
                              void* d_out, int out_size) {
    const float* features = (const float*)d_in[0];
    const float* points   = (const float*)d_in[1];
    const float* kmat     = (const float*)d_in[2];
    const float* rtm      = (const float*)d_in[3];
    const float* Bg       = (const float*)d_in[4];
    const float* W1       = (const float*)d_in[5];
    const float* b1       = (const float*)d_in[6];
    const float* W2       = (const float*)d_in[7];
    const float* b2       = (const float*)d_in[8];
    const float* W3       = (const float*)d_in[9];
    const float* b3       = (const float*)d_in[10];
    const float* W4       = (const float*)d_in[11];
    const float* b4       = (const float*)d_in[12];

    transpose_kernel<<<BATCH * (PIX/32), 256>>>(features);

    const int smem_bytes = SM_FLOATS * 4;  // ~162 KB
    cudaFuncSetAttribute(decoder_kernel, cudaFuncAttributeMaxDynamicSharedMemorySize, smem_bytes);
    decoder_kernel<<<(BATCH*65536)/256, 256, smem_bytes>>>(
        points, kmat, rtm, Bg, W1, b1, W2, b2, W3, b3, W4, b4, (float*)d_out);
}

// round 3
// speedup vs baseline: 1.2000x; 1.2000x over previous
#include <cuda_runtime.h>

typedef unsigned long long u64;

#define FDIM 128
#define HH 56
#define WW 56
#define BATCH 8
#define PIX (HH*WW)   // 3136

// features transposed to (b, y, x, c): bilinear corners become contiguous 512B
__device__ float g_feat[BATCH * PIX * FDIM];

__global__ __launch_bounds__(256) void transpose_kernel(const float* __restrict__ feat) {
    int blk = blockIdx.x;            // 8 * 98 blocks
    int b = blk / 98;
    int pix0 = (blk % 98) * 32;
    __shared__ float tile[FDIM][33];
    int tx = threadIdx.x & 31;
    int ty = threadIdx.x >> 5;
    const float* src = feat + (size_t)b * FDIM * PIX;
    #pragma unroll
    for (int k = 0; k < 16; k++) {
        int c = ty + (k << 3);
        tile[c][tx] = src[c * PIX + pix0 + tx];
    }
    __syncthreads();
    int c2 = threadIdx.x & 127;
    int pg = threadIdx.x >> 7;
    float* dst = g_feat + ((size_t)b * PIX + pix0) * FDIM;
    #pragma unroll
    for (int p = pg; p < 32; p += 2) {
        dst[p * FDIM + c2] = tile[c2][p];
    }
}

// ---------------- packed f32x2 helpers ----------------
__device__ __forceinline__ u64 pack2(float lo, float hi) {
    u64 r; asm("mov.b64 %0, {%1, %2};" : "=l"(r) : "f"(lo), "f"(hi)); return r;
}
__device__ __forceinline__ void unpack2(u64 v, float &lo, float &hi) {
    asm("mov.b64 {%0, %1}, %2;" : "=f"(lo), "=f"(hi) : "l"(v));
}
__device__ __forceinline__ void ffma2(u64 &d, u64 a, u64 b) {
    asm("fma.rn.f32x2 %0, %1, %2, %3;" : "=l"(d) : "l"(a), "l"(b), "l"(d));
}
__device__ __forceinline__ u64 relu2(u64 v) {
    float lo, hi; unpack2(v, lo, hi);
    return pack2(fmaxf(lo, 0.f), fmaxf(hi, 0.f));
}

// ---------------- shared layout (floats) ----------------
#define SM_W2 0
#define SM_W3 4096
#define SM_W4 8192
#define SM_B1 8256
#define SM_B2 8320
#define SM_B3 8384
#define SM_BG 8448
#define SM_H  8640                       // byte 34560, 8B aligned
#define SMEM_BYTES (8640*4 + 32*512*8)   // 34560 + 131072 = 165632

// 256 threads: thread = (pg, side). pg handles 4 consecutive points, side = output half.
__global__ __launch_bounds__(256, 1) void decoder_kernel(
    const float* __restrict__ points, const float* __restrict__ kmat,
    const float* __restrict__ rtm, const float* __restrict__ Bg,
    const float* __restrict__ W1, const float* __restrict__ b1,
    const float* __restrict__ W2, const float* __restrict__ b2,
    const float* __restrict__ W3, const float* __restrict__ b3,
    const float* __restrict__ W4, const float* __restrict__ b4,
    float* __restrict__ out)
{
    extern __shared__ float smf[];
    u64* sH2 = (u64*)(smf + SM_H);
    int tid = threadIdx.x;

    {   // cooperative weight staging (W2, W3 + small vectors)
        float4* d4 = (float4*)(smf + SM_W2);
        const float4* s4 = (const float4*)W2;
        for (int i = tid; i < 1024; i += 256) d4[i] = s4[i];
        d4 = (float4*)(smf + SM_W3); s4 = (const float4*)W3;
        for (int i = tid; i < 1024; i += 256) d4[i] = s4[i];
        if (tid < 64) { smf[SM_W4+tid]=W4[tid]; smf[SM_B1+tid]=b1[tid];
                        smf[SM_B2+tid]=b2[tid]; smf[SM_B3+tid]=b3[tid]; }
        if (tid < 192) smf[SM_BG+tid] = Bg[tid];
    }
    __syncthreads();

    const int side = tid & 1;
    const int pg = tid >> 1;
    const int ptCta = pg * 4;
    const int ptBase = blockIdx.x * 512 + ptCta;
    const int b = ptBase >> 16;

    // ---- per-point projection; each side owns one y-row of corners ----
    float px[4], py[4], pz[4];
    int   cbA[4], cbB[4];
    float cwA[4], cwB[4];
    const float* rtb = rtm + b * 12;
    const float* kb  = kmat + b * 9;
    #pragma unroll
    for (int p = 0; p < 4; p++) {
        int pid = ptBase + p;
        px[p] = points[pid*3+0]; py[p] = points[pid*3+1]; pz[p] = points[pid*3+2];
        float cx = rtb[0]*px[p] + rtb[1]*py[p] + rtb[2]*pz[p] + rtb[3];
        float cy = rtb[4]*px[p] + rtb[5]*py[p] + rtb[6]*pz[p] + rtb[7];
        float cz = rtb[8]*px[p] + rtb[9]*py[p] + rtb[10]*pz[p] + rtb[11];
        float ix = kb[0]*cx + kb[1]*cy + kb[2]*cz;
        float iy = kb[3]*cx + kb[4]*cy + kb[5]*cz;
        float iz = kb[6]*cx + kb[7]*cy + kb[8]*cz;
        float zd = iz + 1e-8f;
        float u = ix / zd, v = iy / zd;
        float valid = (iz > 0.f) ? 1.f : 0.f;
        float un = (2.f*u + 1.f) / (float)WW - 1.f;
        float vn = (2.f*v + 1.f) / (float)HH - 1.f;
        float xs = ((un + 1.f) * (float)WW - 1.f) * 0.5f;
        float ys = ((vn + 1.f) * (float)HH - 1.f) * 0.5f;
        float x0f = floorf(xs), y0f = floorf(ys);
        float fx = xs - x0f, fy = ys - y0f;
        int x0 = (int)x0f, y0 = (int)y0f, x1 = x0 + 1, y1 = y0 + 1;
        float w00 = (1.f-fx)*(1.f-fy);
        float w01 = fx*(1.f-fy);
        float w10 = (1.f-fx)*fy;
        float w11 = fx*fy;
        w00 *= ((x0>=0 && x0<WW && y0>=0 && y0<HH) ? valid : 0.f);
        w01 *= ((x1>=0 && x1<WW && y0>=0 && y0<HH) ? valid : 0.f);
        w10 *= ((x0>=0 && x0<WW && y1>=0 && y1<HH) ? valid : 0.f);
        w11 *= ((x1>=0 && x1<WW && y1>=0 && y1<HH) ? valid : 0.f);
        int x0c = min(max(x0,0),WW-1), x1c = min(max(x1,0),WW-1);
        int y0c = min(max(y0,0),HH-1), y1c = min(max(y1,0),HH-1);
        int yA = side ? y1c : y0c;
        cwA[p] = side ? w10 : w00;
        cwB[p] = side ? w11 : w01;
        cbA[p] = ((b*HH + yA)*WW + x0c) * 32;   // float4 units
        cbB[p] = ((b*HH + yA)*WW + x1c) * 32;
    }

    // ---- layer-1 accumulators: 16 output pairs (this side's 32 neurons) x 4 points ----
    u64 acc[4][16];
    {
        const u64* bb = (const u64*)(smf + SM_B1) + side * 16;
        #pragma unroll
        for (int j = 0; j < 16; j++) {
            u64 v = bb[j];
            acc[0][j] = v; acc[1][j] = v; acc[2][j] = v; acc[3][j] = v;
        }
    }

    // ---- Fourier part: rows 128+m (sin), 192+m (cos); W1 streamed from global ----
    const float TWO_PI = 6.283185307179586f;
    const ulonglong2* wS = (const ulonglong2*)(W1 + 128*64 + side*32);
    const ulonglong2* wC = (const ulonglong2*)(W1 + 192*64 + side*32);
    #pragma unroll 2
    for (int m = 0; m < 64; m++) {
        float g0 = smf[SM_BG+3*m], g1 = smf[SM_BG+3*m+1], g2 = smf[SM_BG+3*m+2];
        u64 sp[4], cp[4];
        #pragma unroll
        for (int p = 0; p < 4; p++) {
            float ang = TWO_PI * (px[p]*g0 + py[p]*g1 + pz[p]*g2);
            float sv, cv; __sincosf(ang, &sv, &cv);
            sp[p] = pack2(sv, sv); cp[p] = pack2(cv, cv);
        }
        #pragma unroll
        for (int j4 = 0; j4 < 8; j4++) {
            ulonglong2 a = wS[m*16 + j4], c = wC[m*16 + j4];
            #pragma unroll
            for (int p = 0; p < 4; p++) {
                ffma2(acc[p][2*j4],   sp[p], a.x);
                ffma2(acc[p][2*j4+1], sp[p], a.y);
                ffma2(acc[p][2*j4],   cp[p], c.x);
                ffma2(acc[p][2*j4+1], cp[p], c.y);
            }
        }
    }

    // ---- image part: each side blends its y-row, exchange with partner via shfl ----
    const float4* g4 = (const float4*)g_feat;
    #pragma unroll 2
    for (int c4 = 0; c4 < 32; c4++) {
        float f[4][4];
        #pragma unroll
        for (int p = 0; p < 4; p++) {
            float4 A  = g4[cbA[p] + c4];
            float4 Bv = g4[cbB[p] + c4];
            f[p][0] = cwA[p]*A.x + cwB[p]*Bv.x;
            f[p][1] = cwA[p]*A.y + cwB[p]*Bv.y;
            f[p][2] = cwA[p]*A.z + cwB[p]*Bv.z;
            f[p][3] = cwA[p]*A.w + cwB[p]*Bv.w;
        }
        #pragma unroll
        for (int p = 0; p < 4; p++)
            #pragma unroll
            for (int s = 0; s < 4; s++)
                f[p][s] += __shfl_xor_sync(0xffffffffu, f[p][s], 1);
        #pragma unroll
        for (int s = 0; s < 4; s++) {
            const ulonglong2* wr = (const ulonglong2*)(W1 + (c4*4+s)*64 + side*32);
            u64 fb[4];
            #pragma unroll
            for (int p = 0; p < 4; p++) fb[p] = pack2(f[p][s], f[p][s]);
            #pragma unroll
            for (int j4 = 0; j4 < 8; j4++) {
                ulonglong2 w = wr[j4];
                #pragma unroll
                for (int p = 0; p < 4; p++) {
                    ffma2(acc[p][2*j4],   fb[p], w.x);
                    ffma2(acc[p][2*j4+1], fb[p], w.y);
                }
            }
        }
    }

    // ---- relu -> shared hidden buffer (32 pair-rows x 512 points) ----
    #pragma unroll
    for (int j = 0; j < 16; j++)
        #pragma unroll
        for (int p = 0; p < 4; p++)
            sH2[(side*16 + j)*512 + ptCta + p] = relu2(acc[p][j]);
    __syncwarp();

    // ---- layer 2 ----
    u64 acc2[4][16];
    {
        const u64* bb = (const u64*)(smf + SM_B2) + side * 16;
        #pragma unroll
        for (int j = 0; j < 16; j++) {
            u64 v = bb[j];
            acc2[0][j] = v; acc2[1][j] = v; acc2[2][j] = v; acc2[3][j] = v;
        }
    }
    #pragma unroll 2
    for (int i2 = 0; i2 < 32; i2++) {
        u64 hb0[4], hb1[4];
        #pragma unroll
        for (int p = 0; p < 4; p++) {
            float h0, h1; unpack2(sH2[i2*512 + ptCta + p], h0, h1);
            hb0[p] = pack2(h0, h0); hb1[p] = pack2(h1, h1);
        }
        const ulonglong2* w0 = (const ulonglong2*)(smf + SM_W2 + (2*i2)*64 + side*32);
        const ulonglong2* w1 = (const ulonglong2*)(smf + SM_W2 + (2*i2+1)*64 + side*32);
        #pragma unroll
        for (int j4 = 0; j4 < 8; j4++) {
            ulonglong2 a = w0[j4], c = w1[j4];
            #pragma unroll
            for (int p = 0; p < 4; p++) {
                ffma2(acc2[p][2*j4],   hb0[p], a.x);
                ffma2(acc2[p][2*j4+1], hb0[p], a.y);
                ffma2(acc2[p][2*j4],   hb1[p], c.x);
                ffma2(acc2[p][2*j4+1], hb1[p], c.y);
            }
        }
    }
    __syncwarp();
    #pragma unroll
    for (int j = 0; j < 16; j++)
        #pragma unroll
        for (int p = 0; p < 4; p++)
            sH2[(side*16 + j)*512 + ptCta + p] = relu2(acc2[p][j]);
    __syncwarp();

    // ---- layer 3 ----
    u64 acc3[4][16];
    {
        const u64* bb = (const u64*)(smf + SM_B3) + side * 16;
        #pragma unroll
        for (int j = 0; j < 16; j++) {
            u64 v = bb[j];
            acc3[0][j] = v; acc3[1][j] = v; acc3[2][j] = v; acc3[3][j] = v;
        }
    }
    #pragma unroll 2
    for (int i2 = 0; i2 < 32; i2++) {
        u64 hb0[4], hb1[4];
        #pragma unroll
        for (int p = 0; p < 4; p++) {
            float h0, h1; unpack2(sH2[i2*512 + ptCta + p], h0, h1);
            hb0[p] = pack2(h0, h0); hb1[p] = pack2(h1, h1);
        }
        const ulonglong2* w0 = (const ulonglong2*)(smf + SM_W3 + (2*i2)*64 + side*32);
        const ulonglong2* w1 = (const ulonglong2*)(smf + SM_W3 + (2*i2+1)*64 + side*32);
        #pragma unroll
        for (int j4 = 0; j4 < 8; j4++) {
            ulonglong2 a = w0[j4], c = w1[j4];
            #pragma unroll
            for (int p = 0; p < 4; p++) {
                ffma2(acc3[p][2*j4],   hb0[p], a.x);
                ffma2(acc3[p][2*j4+1], hb0[p], a.y);
                ffma2(acc3[p][2*j4],   hb1[p], c.x);
                ffma2(acc3[p][2*j4+1], hb1[p], c.y);
            }
        }
    }

    // ---- layer 4: pairwise dot + partner reduce via shfl ----
    const u64* w4p = (const u64*)(smf + SM_W4) + side * 16;
    float bias4 = b4[0];
    float res[4];
    #pragma unroll
    for (int p = 0; p < 4; p++) {
        u64 os = pack2(0.f, 0.f);
        #pragma unroll
        for (int j = 0; j < 16; j++)
            ffma2(os, relu2(acc3[p][j]), w4p[j]);
        float lo, hi; unpack2(os, lo, hi);
        float sum = lo + hi;
        sum += __shfl_xor_sync(0xffffffffu, sum, 1);
        res[p] = sum + bias4;
    }
    if (side == 0)
        *(float4*)(out + ptBase) = make_float4(res[0], res[1], res[2], res[3]);
}

extern "C" void kernel_launch(void* const* d_in, const int* in_sizes, int n_in,
                              void* d_out, int out_size) {
    const float* features = (const float*)d_in[0];
    const float* points   = (const float*)d_in[1];
    const float* kmat     = (const float*)d_in[2];
    const float* rtm      = (const float*)d_in[3];
    const float* Bg       = (const float*)d_in[4];
    const float* W1       = (const float*)d_in[5];
    const float* b1       = (const float*)d_in[6];
    const float* W2       = (const float*)d_in[7];
    const float* b2       = (const float*)d_in[8];
    const float* W3       = (const float*)d_in[9];
    const float* b3       = (const float*)d_in[10];
    const float* W4       = (const float*)d_in[11];
    const float* b4       = (const float*)d_in[12];

    transpose_kernel<<<BATCH * (PIX/32), 256>>>(features);

    cudaFuncSetAttribute(decoder_kernel, cudaFuncAttributeMaxDynamicSharedMemorySize, SMEM_BYTES);
    decoder_kernel<<<(BATCH*65536)/512, 256, SMEM_BYTES>>>(
        points, kmat, rtm, Bg, W1, b1, W2, b2, W3, b3, W4, b4, (float*)d_out);
}

// round 7
// speedup vs baseline: 1.9329x; 1.6107x over previous
#include <cuda_runtime.h>
#include <cuda_bf16.h>
#include <cstdint>

typedef uint32_t u32;

#define FDIM 128
#define HH 56
#define WW 56
#define BATCH 8
#define PIX (HH*WW)

// ---------------- global scratch ----------------
__device__ float g_feat[BATCH * PIX * FDIM];                 // (b,y,x,c)
// W1^T remapped: row n (0..63), k 0..255 (img 0..127, then sin/cos interleaved), stride 264 hw
__device__ __nv_bfloat16 g_w1t[2][64 * 264];
__device__ __nv_bfloat16 g_w2t[2][64 * 72];                  // row n, k 0..63, stride 72 hw
__device__ __nv_bfloat16 g_w3t[2][64 * 72];

// ---------------- transpose features ----------------
__global__ __launch_bounds__(256) void transpose_kernel(const float* __restrict__ feat) {
    int blk = blockIdx.x;
    int b = blk / 98;
    int pix0 = (blk % 98) * 32;
    __shared__ float tile[FDIM][33];
    int tx = threadIdx.x & 31;
    int ty = threadIdx.x >> 5;
    const float* src = feat + (size_t)b * FDIM * PIX;
    #pragma unroll
    for (int k = 0; k < 16; k++) {
        int c = ty + (k << 3);
        tile[c][tx] = src[c * PIX + pix0 + tx];
    }
    __syncthreads();
    int c2 = threadIdx.x & 127;
    int pg = threadIdx.x >> 7;
    float* dst = g_feat + ((size_t)b * PIX + pix0) * FDIM;
    #pragma unroll
    for (int p = pg; p < 32; p += 2) {
        dst[p * FDIM + c2] = tile[c2][p];
    }
}

// ---------------- weight prep: transpose + k-remap + bf16 hi/lo ----------------
__global__ __launch_bounds__(256) void prep_weights(const float* __restrict__ W1,
                                                    const float* __restrict__ W2,
                                                    const float* __restrict__ W3) {
    int t = blockIdx.x * 256 + threadIdx.x;
    if (t < 16384) {                       // W1: [k=256][n=64] -> W1T[n][kk]
        int n = t >> 8, k = t & 255;
        // k-remap: img k<128 unchanged; sin_m -> 128+2m; cos_m -> 129+2m
        int kk = (k < 128) ? k : (k < 192 ? 128 + 2 * (k - 128) : 129 + 2 * (k - 192));
        float w = W1[k * 64 + n];
        float h = __bfloat162float(__float2bfloat16(w));
        g_w1t[0][n * 264 + kk] = __float2bfloat16(h);
        g_w1t[1][n * 264 + kk] = __float2bfloat16(w - h);
    } else if (t < 16384 + 4096) {
        int i = t - 16384;
        int n = i >> 6, k = i & 63;
        float w = W2[k * 64 + n];
        float h = __bfloat162float(__float2bfloat16(w));
        g_w2t[0][n * 72 + k] = __float2bfloat16(h);
        g_w2t[1][n * 72 + k] = __float2bfloat16(w - h);
    } else if (t < 16384 + 8192) {
        int i = t - 20480;
        int n = i >> 6, k = i & 63;
        float w = W3[k * 64 + n];
        float h = __bfloat162float(__float2bfloat16(w));
        g_w3t[0][n * 72 + k] = __float2bfloat16(h);
        g_w3t[1][n * 72 + k] = __float2bfloat16(w - h);
    }
}

// ---------------- helpers ----------------
__device__ __forceinline__ u32 smem_u32(const void* p) {
    u32 a;
    asm("{ .reg .u64 t; cvta.to.shared.u64 t, %1; cvt.u32.u64 %0, t; }" : "=r"(a) : "l"(p));
    return a;
}
__device__ __forceinline__ u32 pack_bf16x2(float lo, float hi) {  // low hw = lo
    u32 r; asm("cvt.rn.bf16x2.f32 %0, %1, %2;" : "=r"(r) : "f"(hi), "f"(lo)); return r;
}
__device__ __forceinline__ void split2(float v, float& h, float& l) {
    h = __bfloat162float(__float2bfloat16(v));
    l = v - h;
}
__device__ __forceinline__ void ldx4(u32* r, u32 addr) {
    asm volatile("ldmatrix.sync.aligned.m8n8.x4.shared.b16 {%0,%1,%2,%3}, [%4];"
        : "=r"(r[0]), "=r"(r[1]), "=r"(r[2]), "=r"(r[3]) : "r"(addr));
}
__device__ __forceinline__ void ldx2(u32* r, u32 addr) {
    asm volatile("ldmatrix.sync.aligned.m8n8.x2.shared.b16 {%0,%1}, [%2];"
        : "=r"(r[0]), "=r"(r[1]) : "r"(addr));
}
__device__ __forceinline__ void mma16816(float* d, const u32* a, const u32* b) {
    asm volatile("mma.sync.aligned.m16n8k16.row.col.f32.bf16.bf16.f32 "
        "{%0,%1,%2,%3}, {%4,%5,%6,%7}, {%8,%9}, {%0,%1,%2,%3};"
        : "+f"(d[0]), "+f"(d[1]), "+f"(d[2]), "+f"(d[3])
        : "r"(a[0]), "r"(a[1]), "r"(a[2]), "r"(a[3]), "r"(b[0]), "r"(b[1]));
}

// ---------------- smem layout (bytes) ----------------
#define S_W1H 0
#define S_W1L 33792
#define S_W2H 67584
#define S_W2L 76800
#define S_W3H 86016
#define S_W3L 95232
#define S_AH  104448            // 256 rows x 144B
#define S_AL  141312
#define S_B1  178176
#define S_B2  178432
#define S_B3  178688
#define S_W4  178944
#define SMEM_SZ 179456

__global__ __launch_bounds__(256, 1) void decoder_kernel(
    const float* __restrict__ points, const float* __restrict__ kmat,
    const float* __restrict__ rtm, const float* __restrict__ Bg,
    const float* __restrict__ b1, const float* __restrict__ b2,
    const float* __restrict__ b3, const float* __restrict__ W4,
    const float* __restrict__ b4, float* __restrict__ out)
{
    extern __shared__ __align__(16) unsigned char sm[];
    const u32 sbase = smem_u32(sm);
    const int tid = threadIdx.x;
    const int warp = tid >> 5;
    const int lane = tid & 31;

    // ---- stage weights ----
    {
        uint4* d4; const uint4* s4;
        d4 = (uint4*)(sm + S_W1H); s4 = (const uint4*)g_w1t[0];
        for (int i = tid; i < 2112; i += 256) d4[i] = s4[i];
        d4 = (uint4*)(sm + S_W1L); s4 = (const uint4*)g_w1t[1];
        for (int i = tid; i < 2112; i += 256) d4[i] = s4[i];
        d4 = (uint4*)(sm + S_W2H); s4 = (const uint4*)g_w2t[0];
        for (int i = tid; i < 576; i += 256) d4[i] = s4[i];
        d4 = (uint4*)(sm + S_W2L); s4 = (const uint4*)g_w2t[1];
        for (int i = tid; i < 576; i += 256) d4[i] = s4[i];
        d4 = (uint4*)(sm + S_W3H); s4 = (const uint4*)g_w3t[0];
        for (int i = tid; i < 576; i += 256) d4[i] = s4[i];
        d4 = (uint4*)(sm + S_W3L); s4 = (const uint4*)g_w3t[1];
        for (int i = tid; i < 576; i += 256) d4[i] = s4[i];
        if (tid < 64) {
            ((float*)(sm + S_B1))[tid] = b1[tid];
            ((float*)(sm + S_B2))[tid] = b2[tid];
            ((float*)(sm + S_B3))[tid] = b3[tid];
            ((float*)(sm + S_W4))[tid] = W4[tid];
        }
    }

    // ---- per-thread point projection (1 point / thread, 256 points / CTA) ----
    const int ctaBase = blockIdx.x * 256;
    const int pid = ctaBase + tid;
    const int b = pid >> 16;
    float px = points[pid*3+0], py = points[pid*3+1], pz = points[pid*3+2];
    int c00, c01, c10, c11;
    float w00, w01, w10, w11;
    {
        const float* rtb = rtm + b * 12;
        const float* kb = kmat + b * 9;
        float cx = rtb[0]*px + rtb[1]*py + rtb[2]*pz + rtb[3];
        float cy = rtb[4]*px + rtb[5]*py + rtb[6]*pz + rtb[7];
        float cz = rtb[8]*px + rtb[9]*py + rtb[10]*pz + rtb[11];
        float ix = kb[0]*cx + kb[1]*cy + kb[2]*cz;
        float iy = kb[3]*cx + kb[4]*cy + kb[5]*cz;
        float iz = kb[6]*cx + kb[7]*cy + kb[8]*cz;
        float zd = iz + 1e-8f;
        float u = ix / zd, v = iy / zd;
        float valid = (iz > 0.f) ? 1.f : 0.f;
        float un = (2.f*u + 1.f) / (float)WW - 1.f;
        float vn = (2.f*v + 1.f) / (float)HH - 1.f;
        float xs = ((un + 1.f) * (float)WW - 1.f) * 0.5f;
        float ys = ((vn + 1.f) * (float)HH - 1.f) * 0.5f;
        float x0f = floorf(xs), y0f = floorf(ys);
        float fx = xs - x0f, fy = ys - y0f;
        int x0 = (int)x0f, y0 = (int)y0f, x1 = x0 + 1, y1 = y0 + 1;
        w00 = (1.f-fx)*(1.f-fy); w01 = fx*(1.f-fy); w10 = (1.f-fx)*fy; w11 = fx*fy;
        w00 *= ((x0>=0 && x0<WW && y0>=0 && y0<HH) ? valid : 0.f);
        w01 *= ((x1>=0 && x1<WW && y0>=0 && y0<HH) ? valid : 0.f);
        w10 *= ((x0>=0 && x0<WW && y1>=0 && y1<HH) ? valid : 0.f);
        w11 *= ((x1>=0 && x1<WW && y1>=0 && y1<HH) ? valid : 0.f);
        int x0c = min(max(x0,0),WW-1), x1c = min(max(x1,0),WW-1);
        int y0c = min(max(y0,0),HH-1), y1c = min(max(y1,0),HH-1);
        c00 = ((b*HH + y0c)*WW + x0c) * 32;
        c01 = ((b*HH + y0c)*WW + x1c) * 32;
        c10 = ((b*HH + y1c)*WW + x0c) * 32;
        c11 = ((b*HH + y1c)*WW + x1c) * 32;
    }

    // ---- layer-1: stream K in 4 chunks of 64, mma accumulate ----
    const int wm = warp * 32;
    float D[2][8][4];
    #pragma unroll
    for (int mt = 0; mt < 2; mt++)
        #pragma unroll
        for (int nt = 0; nt < 8; nt++)
            #pragma unroll
            for (int q = 0; q < 4; q++) D[mt][nt][q] = 0.f;

    const float4* g4 = (const float4*)g_feat;
    const float TWO_PI = 6.283185307179586f;

    #pragma unroll 1
    for (int c = 0; c < 4; c++) {
        // --- produce chunk: 64 features for this thread's point ---
        if (c < 2) {
            #pragma unroll
            for (int q = 0; q < 16; q++) {
                int c4 = c * 16 + q;
                float4 A = g4[c00 + c4], B = g4[c01 + c4], C = g4[c10 + c4], E = g4[c11 + c4];
                float f0 = w00*A.x + w01*B.x + w10*C.x + w11*E.x;
                float f1 = w00*A.y + w01*B.y + w10*C.y + w11*E.y;
                float f2 = w00*A.z + w01*B.z + w10*C.z + w11*E.z;
                float f3 = w00*A.w + w01*B.w + w10*C.w + w11*E.w;
                float h0,l0,h1,l1,h2,l2,h3,l3;
                split2(f0,h0,l0); split2(f1,h1,l1); split2(f2,h2,l2); split2(f3,h3,l3);
                *(u32*)(sm + S_AH + tid*144 + q*8)     = pack_bf16x2(h0, h1);
                *(u32*)(sm + S_AH + tid*144 + q*8 + 4) = pack_bf16x2(h2, h3);
                *(u32*)(sm + S_AL + tid*144 + q*8)     = pack_bf16x2(l0, l1);
                *(u32*)(sm + S_AL + tid*144 + q*8 + 4) = pack_bf16x2(l2, l3);
            }
        } else {
            int mbase = (c - 2) * 32;
            #pragma unroll
            for (int q = 0; q < 16; q++) {
                int m = mbase + 2 * q;
                float a0 = TWO_PI * (px*__ldg(Bg+3*m)   + py*__ldg(Bg+3*m+1) + pz*__ldg(Bg+3*m+2));
                float a1 = TWO_PI * (px*__ldg(Bg+3*m+3) + py*__ldg(Bg+3*m+4) + pz*__ldg(Bg+3*m+5));
                float s0, cc0, s1, cc1;
                __sincosf(a0, &s0, &cc0);
                __sincosf(a1, &s1, &cc1);
                float h0,l0,h1,l1,h2,l2,h3,l3;
                split2(s0,h0,l0); split2(cc0,h1,l1); split2(s1,h2,l2); split2(cc1,h3,l3);
                *(u32*)(sm + S_AH + tid*144 + q*8)     = pack_bf16x2(h0, h1);
                *(u32*)(sm + S_AH + tid*144 + q*8 + 4) = pack_bf16x2(h2, h3);
                *(u32*)(sm + S_AL + tid*144 + q*8)     = pack_bf16x2(l0, l1);
                *(u32*)(sm + S_AL + tid*144 + q*8 + 4) = pack_bf16x2(l2, l3);
            }
        }
        __syncthreads();

        // --- consume chunk: 4 k-steps of 16 ---
        #pragma unroll
        for (int ks = 0; ks < 4; ks++) {
            int k0b = ks * 32;                           // bytes within chunk
            u32 ah[2][4], al[2][4];
            u32 arow = wm + (lane & 15);
            u32 akb = k0b + ((lane >> 4) << 4);
            ldx4(ah[0], sbase + S_AH + arow*144 + akb);
            ldx4(al[0], sbase + S_AL + arow*144 + akb);
            ldx4(ah[1], sbase + S_AH + (arow+16)*144 + akb);
            ldx4(al[1], sbase + S_AL + (arow+16)*144 + akb);
            #pragma unroll
            for (int nt = 0; nt < 8; nt++) {
                u32 brow = nt*8 + (lane & 7);
                u32 bkb = c*128 + k0b + ((lane & 8) ? 16 : 0);
                u32 bh[2], bl[2];
                ldx2(bh, sbase + S_W1H + brow*528 + bkb);
                ldx2(bl, sbase + S_W1L + brow*528 + bkb);
                mma16816(D[0][nt], ah[0], bh);
                mma16816(D[1][nt], ah[1], bh);
                mma16816(D[0][nt], ah[0], bl);
                mma16816(D[1][nt], ah[1], bl);
                mma16816(D[0][nt], al[0], bh);
                mma16816(D[1][nt], al[1], bh);
            }
        }
        __syncthreads();
    }

    const int g = lane >> 2;
    const int qc = lane & 3;

    // ---- epilogue 1: relu(D + b1) -> bf16 hi/lo back into A buffer ----
    {
        const float* B1 = (const float*)(sm + S_B1);
        #pragma unroll
        for (int mt = 0; mt < 2; mt++) {
            int row0 = wm + mt*16 + g;
            #pragma unroll
            for (int nt = 0; nt < 8; nt++) {
                int n0 = nt*8 + qc*2;
                float v0 = fmaxf(D[mt][nt][0] + B1[n0],   0.f);
                float v1 = fmaxf(D[mt][nt][1] + B1[n0+1], 0.f);
                float v2 = fmaxf(D[mt][nt][2] + B1[n0],   0.f);
                float v3 = fmaxf(D[mt][nt][3] + B1[n0+1], 0.f);
                float h0,l0,h1,l1,h2,l2,h3,l3;
                split2(v0,h0,l0); split2(v1,h1,l1); split2(v2,h2,l2); split2(v3,h3,l3);
                *(u32*)(sm + S_AH + row0*144 + n0*2)     = pack_bf16x2(h0, h1);
                *(u32*)(sm + S_AL + row0*144 + n0*2)     = pack_bf16x2(l0, l1);
                *(u32*)(sm + S_AH + (row0+8)*144 + n0*2) = pack_bf16x2(h2, h3);
                *(u32*)(sm + S_AL + (row0+8)*144 + n0*2) = pack_bf16x2(l2, l3);
                D[mt][nt][0] = 0.f; D[mt][nt][1] = 0.f; D[mt][nt][2] = 0.f; D[mt][nt][3] = 0.f;
            }
        }
    }
    __syncthreads();

    // ---- layers 2 and 3 (K = 64) ----
    #pragma unroll 1
    for (int layer = 0; layer < 2; layer++) {
        u32 wH = sbase + (layer == 0 ? S_W2H : S_W3H);
        u32 wL = sbase + (layer == 0 ? S_W2L : S_W3L);
        #pragma unroll
        for (int ks = 0; ks < 4; ks++) {
            int k0b = ks * 32;
            u32 ah[2][4], al[2][4];
            u32 arow = wm + (lane & 15);
            u32 akb = k0b + ((lane >> 4) << 4);
            ldx4(ah[0], sbase + S_AH + arow*144 + akb);
            ldx4(al[0], sbase + S_AL + arow*144 + akb);
            ldx4(ah[1], sbase + S_AH + (arow+16)*144 + akb);
            ldx4(al[1], sbase + S_AL + (arow+16)*144 + akb);
            #pragma unroll
            for (int nt = 0; nt < 8; nt++) {
                u32 brow = nt*8 + (lane & 7);
                u32 bkb = k0b + ((lane & 8) ? 16 : 0);
                u32 bh[2], bl[2];
                ldx2(bh, wH + brow*144 + bkb);
                ldx2(bl, wL + brow*144 + bkb);
                mma16816(D[0][nt], ah[0], bh);
                mma16816(D[1][nt], ah[1], bh);
                mma16816(D[0][nt], ah[0], bl);
                mma16816(D[1][nt], ah[1], bl);
                mma16816(D[0][nt], al[0], bh);
                mma16816(D[1][nt], al[1], bh);
            }
        }
        __syncthreads();

        if (layer == 0) {
            // epilogue 2 -> buffer
            const float* B2 = (const float*)(sm + S_B2);
            #pragma unroll
            for (int mt = 0; mt < 2; mt++) {
                int row0 = wm + mt*16 + g;
                #pragma unroll
                for (int nt = 0; nt < 8; nt++) {
                    int n0 = nt*8 + qc*2;
                    float v0 = fmaxf(D[mt][nt][0] + B2[n0],   0.f);
                    float v1 = fmaxf(D[mt][nt][1] + B2[n0+1], 0.f);
                    float v2 = fmaxf(D[mt][nt][2] + B2[n0],   0.f);
                    float v3 = fmaxf(D[mt][nt][3] + B2[n0+1], 0.f);
                    float h0,l0,h1,l1,h2,l2,h3,l3;
                    split2(v0,h0,l0); split2(v1,h1,l1); split2(v2,h2,l2); split2(v3,h3,l3);
                    *(u32*)(sm + S_AH + row0*144 + n0*2)     = pack_bf16x2(h0, h1);
                    *(u32*)(sm + S_AL + row0*144 + n0*2)     = pack_bf16x2(l0, l1);
                    *(u32*)(sm + S_AH + (row0+8)*144 + n0*2) = pack_bf16x2(h2, h3);
                    *(u32*)(sm + S_AL + (row0+8)*144 + n0*2) = pack_bf16x2(l2, l3);
                    D[mt][nt][0] = 0.f; D[mt][nt][1] = 0.f; D[mt][nt][2] = 0.f; D[mt][nt][3] = 0.f;
                }
            }
            __syncthreads();
        }
    }

    // ---- epilogue 3: out = relu(D + b3) . W4 + b4 ----
    {
        const float* B3 = (const float*)(sm + S_B3);
        const float* W4s = (const float*)(sm + S_W4);
        float b4v = b4[0];
        #pragma unroll
        for (int mt = 0; mt < 2; mt++) {
            float p0 = 0.f, p1 = 0.f;
            #pragma unroll
            for (int nt = 0; nt < 8; nt++) {
                int n0 = nt*8 + qc*2;
                p0 += fmaxf(D[mt][nt][0] + B3[n0],   0.f) * W4s[n0];
                p0 += fmaxf(D[mt][nt][1] + B3[n0+1], 0.f) * W4s[n0+1];
                p1 += fmaxf(D[mt][nt][2] + B3[n0],   0.f) * W4s[n0];
                p1 += fmaxf(D[mt][nt][3] + B3[n0+1], 0.f) * W4s[n0+1];
            }
            p0 += __shfl_xor_sync(0xffffffffu, p0, 1);
            p0 += __shfl_xor_sync(0xffffffffu, p0, 2);
            p1 += __shfl_xor_sync(0xffffffffu, p1, 1);
            p1 += __shfl_xor_sync(0xffffffffu, p1, 2);
            if (qc == 0) {
                out[ctaBase + wm + mt*16 + g]     = p0 + b4v;
                out[ctaBase + wm + mt*16 + g + 8] = p1 + b4v;
            }
        }
    }
}

extern "C" void kernel_launch(void* const* d_in, const int* in_sizes, int n_in,
                              void* d_out, int out_size) {
    const float* features = (const float*)d_in[0];
    const float* points   = (const float*)d_in[1];
    const float* kmat     = (const float*)d_in[2];
    const float* rtm      = (const float*)d_in[3];
    const float* Bg       = (const float*)d_in[4];
    const float* W1       = (const float*)d_in[5];
    const float* b1       = (const float*)d_in[6];
    const float* W2       = (const float*)d_in[7];
    const float* b2       = (const float*)d_in[8];
    const float* W3       = (const float*)d_in[9];
    const float* b3       = (const float*)d_in[10];
    const float* W4       = (const float*)d_in[11];
    const float* b4       = (const float*)d_in[12];

    transpose_kernel<<<BATCH * (PIX/32), 256>>>(features);
    prep_weights<<<96, 256>>>(W1, W2, W3);

    cudaFuncSetAttribute(decoder_kernel, cudaFuncAttributeMaxDynamicSharedMemorySize, SMEM_SZ);
    decoder_kernel<<<(BATCH*65536)/256, 256, SMEM_SZ>>>(
        points, kmat, rtm, Bg, b1, b2, b3, W4, b4, (float*)d_out);
}

// round 8
// speedup vs baseline: 2.8537x; 1.4764x over previous
#include <cuda_runtime.h>
#include <cuda_bf16.h>
#include <cstdint>

typedef uint32_t u32;

#define FDIM 128
#define HH 56
#define WW 56
#define BATCH 8
#define PIX (HH*WW)

// ---------------- global scratch ----------------
__device__ float g_feat[BATCH * PIX * FDIM];                 // (b,y,x,c)
__device__ __nv_bfloat16 g_w1t[2][64 * 264];                 // W1^T remapped, stride 264 hw
__device__ __nv_bfloat16 g_w2t[2][64 * 72];                  // W2^T, stride 72 hw
__device__ __nv_bfloat16 g_w3t[2][64 * 72];

// ---------------- transpose features ----------------
__global__ __launch_bounds__(256) void transpose_kernel(const float* __restrict__ feat) {
    int blk = blockIdx.x;
    int b = blk / 98;
    int pix0 = (blk % 98) * 32;
    __shared__ float tile[FDIM][33];
    int tx = threadIdx.x & 31;
    int ty = threadIdx.x >> 5;
    const float* src = feat + (size_t)b * FDIM * PIX;
    #pragma unroll
    for (int k = 0; k < 16; k++) {
        int c = ty + (k << 3);
        tile[c][tx] = src[c * PIX + pix0 + tx];
    }
    __syncthreads();
    int c2 = threadIdx.x & 127;
    int pg = threadIdx.x >> 7;
    float* dst = g_feat + ((size_t)b * PIX + pix0) * FDIM;
    #pragma unroll
    for (int p = pg; p < 32; p += 2) {
        dst[p * FDIM + c2] = tile[c2][p];
    }
}

// ---------------- weight prep ----------------
__global__ __launch_bounds__(256) void prep_weights(const float* __restrict__ W1,
                                                    const float* __restrict__ W2,
                                                    const float* __restrict__ W3) {
    int t = blockIdx.x * 256 + threadIdx.x;
    if (t < 16384) {                       // W1: [k=256][n=64] -> W1T[n][kk]
        int n = t >> 8, k = t & 255;
        int kk = (k < 128) ? k : (k < 192 ? 128 + 2 * (k - 128) : 129 + 2 * (k - 192));
        float w = W1[k * 64 + n];
        float h = __bfloat162float(__float2bfloat16(w));
        g_w1t[0][n * 264 + kk] = __float2bfloat16(h);
        g_w1t[1][n * 264 + kk] = __float2bfloat16(w - h);
    } else if (t < 16384 + 4096) {
        int i = t - 16384;
        int n = i >> 6, k = i & 63;
        float w = W2[k * 64 + n];
        float h = __bfloat162float(__float2bfloat16(w));
        g_w2t[0][n * 72 + k] = __float2bfloat16(h);
        g_w2t[1][n * 72 + k] = __float2bfloat16(w - h);
    } else if (t < 16384 + 8192) {
        int i = t - 20480;
        int n = i >> 6, k = i & 63;
        float w = W3[k * 64 + n];
        float h = __bfloat162float(__float2bfloat16(w));
        g_w3t[0][n * 72 + k] = __float2bfloat16(h);
        g_w3t[1][n * 72 + k] = __float2bfloat16(w - h);
    }
}

// ---------------- helpers ----------------
__device__ __forceinline__ u32 smem_u32(const void* p) {
    u32 a;
    asm("{ .reg .u64 t; cvta.to.shared.u64 t, %1; cvt.u32.u64 %0, t; }" : "=r"(a) : "l"(p));
    return a;
}
__device__ __forceinline__ u32 pack_bf16x2(float lo, float hi) {
    u32 r; asm("cvt.rn.bf16x2.f32 %0, %1, %2;" : "=r"(r) : "f"(hi), "f"(lo)); return r;
}
__device__ __forceinline__ void split2(float v, float& h, float& l) {
    h = __bfloat162float(__float2bfloat16(v));
    l = v - h;
}
__device__ __forceinline__ void ldx4(u32* r, u32 addr) {
    asm volatile("ldmatrix.sync.aligned.m8n8.x4.shared.b16 {%0,%1,%2,%3}, [%4];"
        : "=r"(r[0]), "=r"(r[1]), "=r"(r[2]), "=r"(r[3]) : "r"(addr));
}
__device__ __forceinline__ void mma16816(float* d, const u32* a, const u32* b) {
    asm volatile("mma.sync.aligned.m16n8k16.row.col.f32.bf16.bf16.f32 "
        "{%0,%1,%2,%3}, {%4,%5,%6,%7}, {%8,%9}, {%0,%1,%2,%3};"
        : "+f"(d[0]), "+f"(d[1]), "+f"(d[2]), "+f"(d[3])
        : "r"(a[0]), "r"(a[1]), "r"(a[2]), "r"(a[3]), "r"(b[0]), "r"(b[1]));
}

// ---------------- smem layout (bytes) ----------------
#define S_W1H 0
#define S_W1L 33792
#define S_W2H 67584
#define S_W2L 76800
#define S_W3H 86016
#define S_W3L 95232
#define S_AH  104448            // 256 rows x 144B (chunk buffer)
#define S_AL  141312
#define S_B1  178176
#define S_B2  178432
#define S_B3  178688
#define S_W4  178944
#define S_PAR 179200            // 256 points x 8 words (c00..c11, w00..w11)
#define SMEM_SZ (179200 + 8192)

__global__ __launch_bounds__(256, 1) void decoder_kernel(
    const float* __restrict__ points, const float* __restrict__ kmat,
    const float* __restrict__ rtm, const float* __restrict__ Bg,
    const float* __restrict__ b1, const float* __restrict__ b2,
    const float* __restrict__ b3, const float* __restrict__ W4,
    const float* __restrict__ b4, float* __restrict__ out)
{
    extern __shared__ __align__(16) unsigned char sm[];
    const u32 sbase = smem_u32(sm);
    const int tid = threadIdx.x;
    const int warp = tid >> 5;
    const int lane = tid & 31;

    // ---- stage weights (CTA cooperative) ----
    {
        uint4* d4; const uint4* s4;
        d4 = (uint4*)(sm + S_W1H); s4 = (const uint4*)g_w1t[0];
        for (int i = tid; i < 2112; i += 256) d4[i] = s4[i];
        d4 = (uint4*)(sm + S_W1L); s4 = (const uint4*)g_w1t[1];
        for (int i = tid; i < 2112; i += 256) d4[i] = s4[i];
        d4 = (uint4*)(sm + S_W2H); s4 = (const uint4*)g_w2t[0];
        for (int i = tid; i < 576; i += 256) d4[i] = s4[i];
        d4 = (uint4*)(sm + S_W2L); s4 = (const uint4*)g_w2t[1];
        for (int i = tid; i < 576; i += 256) d4[i] = s4[i];
        d4 = (uint4*)(sm + S_W3H); s4 = (const uint4*)g_w3t[0];
        for (int i = tid; i < 576; i += 256) d4[i] = s4[i];
        d4 = (uint4*)(sm + S_W3L); s4 = (const uint4*)g_w3t[1];
        for (int i = tid; i < 576; i += 256) d4[i] = s4[i];
        if (tid < 64) {
            ((float*)(sm + S_B1))[tid] = b1[tid];
            ((float*)(sm + S_B2))[tid] = b2[tid];
            ((float*)(sm + S_B3))[tid] = b3[tid];
            ((float*)(sm + S_W4))[tid] = W4[tid];
        }
    }

    // ---- projection: own point -> params table (warp-private consumption) ----
    const int ctaBase = blockIdx.x * 256;
    const int pid = ctaBase + tid;
    const int b = pid >> 16;
    float px = points[pid*3+0], py = points[pid*3+1], pz = points[pid*3+2];
    {
        const float* rtb = rtm + b * 12;
        const float* kb = kmat + b * 9;
        float cx = rtb[0]*px + rtb[1]*py + rtb[2]*pz + rtb[3];
        float cy = rtb[4]*px + rtb[5]*py + rtb[6]*pz + rtb[7];
        float cz = rtb[8]*px + rtb[9]*py + rtb[10]*pz + rtb[11];
        float ix = kb[0]*cx + kb[1]*cy + kb[2]*cz;
        float iy = kb[3]*cx + kb[4]*cy + kb[5]*cz;
        float iz = kb[6]*cx + kb[7]*cy + kb[8]*cz;
        float zd = iz + 1e-8f;
        float u = ix / zd, v = iy / zd;
        float valid = (iz > 0.f) ? 1.f : 0.f;
        float un = (2.f*u + 1.f) / (float)WW - 1.f;
        float vn = (2.f*v + 1.f) / (float)HH - 1.f;
        float xs = ((un + 1.f) * (float)WW - 1.f) * 0.5f;
        float ys = ((vn + 1.f) * (float)HH - 1.f) * 0.5f;
        float x0f = floorf(xs), y0f = floorf(ys);
        float fx = xs - x0f, fy = ys - y0f;
        int x0 = (int)x0f, y0 = (int)y0f, x1 = x0 + 1, y1 = y0 + 1;
        float w00 = (1.f-fx)*(1.f-fy), w01 = fx*(1.f-fy), w10 = (1.f-fx)*fy, w11 = fx*fy;
        w00 *= ((x0>=0 && x0<WW && y0>=0 && y0<HH) ? valid : 0.f);
        w01 *= ((x1>=0 && x1<WW && y0>=0 && y0<HH) ? valid : 0.f);
        w10 *= ((x0>=0 && x0<WW && y1>=0 && y1<HH) ? valid : 0.f);
        w11 *= ((x1>=0 && x1<WW && y1>=0 && y1<HH) ? valid : 0.f);
        int x0c = min(max(x0,0),WW-1), x1c = min(max(x1,0),WW-1);
        int y0c = min(max(y0,0),HH-1), y1c = min(max(y1,0),HH-1);
        int4* pi = (int4*)(sm + S_PAR + tid*32);
        float4* pf = (float4*)(sm + S_PAR + tid*32 + 16);
        *pi = make_int4(((b*HH + y0c)*WW + x0c) * 32, ((b*HH + y0c)*WW + x1c) * 32,
                        ((b*HH + y1c)*WW + x0c) * 32, ((b*HH + y1c)*WW + x1c) * 32);
        *pf = make_float4(w00, w01, w10, w11);
    }
    __syncthreads();   // the only CTA barrier: weights + params visible

    // ---- layer-1: stream K in 4 chunks of 64, warp-private produce/consume ----
    const int wm = warp * 32;
    float D[2][8][4];
    #pragma unroll
    for (int mt = 0; mt < 2; mt++)
        #pragma unroll
        for (int nt = 0; nt < 8; nt++)
            #pragma unroll
            for (int q = 0; q < 4; q++) D[mt][nt][q] = 0.f;

    const float4* g4 = (const float4*)g_feat;
    const float TWO_PI = 6.283185307179586f;
    const int half = lane >> 4;        // gather: which of 2 points
    const int slot = lane & 15;        // float4 slot within chunk

    #pragma unroll 1
    for (int c = 0; c < 4; c++) {
        if (c < 2) {
            // --- cooperative coalesced gather: 2 points/iter, lanes cover channels ---
            #pragma unroll 2
            for (int pp = 0; pp < 32; pp += 2) {
                int t = wm + pp + half;
                const int4 ci = *(const int4*)(sm + S_PAR + t*32);
                const float4 cw = *(const float4*)(sm + S_PAR + t*32 + 16);
                int c4 = c * 16 + slot;
                float4 A = g4[ci.x + c4];
                float4 B = g4[ci.y + c4];
                float4 C = g4[ci.z + c4];
                float4 E = g4[ci.w + c4];
                float f0 = cw.x*A.x + cw.y*B.x + cw.z*C.x + cw.w*E.x;
                float f1 = cw.x*A.y + cw.y*B.y + cw.z*C.y + cw.w*E.y;
                float f2 = cw.x*A.z + cw.y*B.z + cw.z*C.z + cw.w*E.z;
                float f3 = cw.x*A.w + cw.y*B.w + cw.z*C.w + cw.w*E.w;
                float h0,l0,h1,l1,h2,l2,h3,l3;
                split2(f0,h0,l0); split2(f1,h1,l1); split2(f2,h2,l2); split2(f3,h3,l3);
                u32* dh = (u32*)(sm + S_AH + t*144 + slot*8);
                u32* dl = (u32*)(sm + S_AL + t*144 + slot*8);
                dh[0] = pack_bf16x2(h0, h1); dh[1] = pack_bf16x2(h2, h3);
                dl[0] = pack_bf16x2(l0, l1); dl[1] = pack_bf16x2(l2, l3);
            }
        } else {
            // --- Fourier: per-thread own row (warp-private) ---
            int mbase = (c - 2) * 32;
            #pragma unroll
            for (int q = 0; q < 16; q++) {
                int m = mbase + 2 * q;
                float a0 = TWO_PI * (px*__ldg(Bg+3*m)   + py*__ldg(Bg+3*m+1) + pz*__ldg(Bg+3*m+2));
                float a1 = TWO_PI * (px*__ldg(Bg+3*m+3) + py*__ldg(Bg+3*m+4) + pz*__ldg(Bg+3*m+5));
                float s0, cc0, s1, cc1;
                __sincosf(a0, &s0, &cc0);
                __sincosf(a1, &s1, &cc1);
                float h0,l0,h1,l1,h2,l2,h3,l3;
                split2(s0,h0,l0); split2(cc0,h1,l1); split2(s1,h2,l2); split2(cc1,h3,l3);
                u32* dh = (u32*)(sm + S_AH + tid*144 + q*8);
                u32* dl = (u32*)(sm + S_AL + tid*144 + q*8);
                dh[0] = pack_bf16x2(h0, h1); dh[1] = pack_bf16x2(h2, h3);
                dl[0] = pack_bf16x2(l0, l1); dl[1] = pack_bf16x2(l2, l3);
            }
        }
        __syncwarp();

        // --- consume chunk: 4 k-steps of 16, B via x4 ldmatrix (2 n-tiles/inst) ---
        #pragma unroll
        for (int ks = 0; ks < 4; ks++) {
            int k0b = ks * 32;
            u32 ah[2][4], al[2][4];
            u32 arow = wm + (lane & 15);
            u32 akb = k0b + ((lane >> 4) << 4);
            ldx4(ah[0], sbase + S_AH + arow*144 + akb);
            ldx4(al[0], sbase + S_AL + arow*144 + akb);
            ldx4(ah[1], sbase + S_AH + (arow+16)*144 + akb);
            ldx4(al[1], sbase + S_AL + (arow+16)*144 + akb);
            u32 brow = (lane & 7) + ((lane >> 4) << 3);         // row within 16-row pair
            u32 bk = c*128 + k0b + (((lane >> 3) & 1) << 4);    // +16B for k8 half
            #pragma unroll
            for (int ntp = 0; ntp < 4; ntp++) {
                u32 baddr = (ntp*16 + brow) * 528 + bk;
                u32 bh[4], bl[4];
                ldx4(bh, sbase + S_W1H + baddr);
                ldx4(bl, sbase + S_W1L + baddr);
                int nt = 2 * ntp;
                mma16816(D[0][nt],   ah[0], bh+0);
                mma16816(D[1][nt],   ah[1], bh+0);
                mma16816(D[0][nt],   ah[0], bl+0);
                mma16816(D[1][nt],   ah[1], bl+0);
                mma16816(D[0][nt],   al[0], bh+0);
                mma16816(D[1][nt],   al[1], bh+0);
                mma16816(D[0][nt+1], ah[0], bh+2);
                mma16816(D[1][nt+1], ah[1], bh+2);
                mma16816(D[0][nt+1], ah[0], bl+2);
                mma16816(D[1][nt+1], ah[1], bl+2);
                mma16816(D[0][nt+1], al[0], bh+2);
                mma16816(D[1][nt+1], al[1], bh+2);
            }
        }
        __syncwarp();
    }

    const int g = lane >> 2;
    const int qc = lane & 3;

    // ---- epilogue 1: relu(D + b1) -> bf16 hi/lo back into A buffer (own rows) ----
    {
        const float* B1 = (const float*)(sm + S_B1);
        #pragma unroll
        for (int mt = 0; mt < 2; mt++) {
            int row0 = wm + mt*16 + g;
            #pragma unroll
            for (int nt = 0; nt < 8; nt++) {
                int n0 = nt*8 + qc*2;
                float v0 = fmaxf(D[mt][nt][0] + B1[n0],   0.f);
                float v1 = fmaxf(D[mt][nt][1] + B1[n0+1], 0.f);
                float v2 = fmaxf(D[mt][nt][2] + B1[n0],   0.f);
                float v3 = fmaxf(D[mt][nt][3] + B1[n0+1], 0.f);
                float h0,l0,h1,l1,h2,l2,h3,l3;
                split2(v0,h0,l0); split2(v1,h1,l1); split2(v2,h2,l2); split2(v3,h3,l3);
                *(u32*)(sm + S_AH + row0*144 + n0*2)     = pack_bf16x2(h0, h1);
                *(u32*)(sm + S_AL + row0*144 + n0*2)     = pack_bf16x2(l0, l1);
                *(u32*)(sm + S_AH + (row0+8)*144 + n0*2) = pack_bf16x2(h2, h3);
                *(u32*)(sm + S_AL + (row0+8)*144 + n0*2) = pack_bf16x2(l2, l3);
                D[mt][nt][0] = 0.f; D[mt][nt][1] = 0.f; D[mt][nt][2] = 0.f; D[mt][nt][3] = 0.f;
            }
        }
    }
    __syncwarp();

    // ---- layers 2 and 3 (K = 64), warp-private ----
    #pragma unroll 1
    for (int layer = 0; layer < 2; layer++) {
        u32 wH = sbase + (layer == 0 ? S_W2H : S_W3H);
        u32 wL = sbase + (layer == 0 ? S_W2L : S_W3L);
        #pragma unroll
        for (int ks = 0; ks < 4; ks++) {
            int k0b = ks * 32;
            u32 ah[2][4], al[2][4];
            u32 arow = wm + (lane & 15);
            u32 akb = k0b + ((lane >> 4) << 4);
            ldx4(ah[0], sbase + S_AH + arow*144 + akb);
            ldx4(al[0], sbase + S_AL + arow*144 + akb);
            ldx4(ah[1], sbase + S_AH + (arow+16)*144 + akb);
            ldx4(al[1], sbase + S_AL + (arow+16)*144 + akb);
            u32 brow = (lane & 7) + ((lane >> 4) << 3);
            u32 bk = k0b + (((lane >> 3) & 1) << 4);
            #pragma unroll
            for (int ntp = 0; ntp < 4; ntp++) {
                u32 baddr = (ntp*16 + brow) * 144 + bk;
                u32 bh[4], bl[4];
                ldx4(bh, wH + baddr);
                ldx4(bl, wL + baddr);
                int nt = 2 * ntp;
                mma16816(D[0][nt],   ah[0], bh+0);
                mma16816(D[1][nt],   ah[1], bh+0);
                mma16816(D[0][nt],   ah[0], bl+0);
                mma16816(D[1][nt],   ah[1], bl+0);
                mma16816(D[0][nt],   al[0], bh+0);
                mma16816(D[1][nt],   al[1], bh+0);
                mma16816(D[0][nt+1], ah[0], bh+2);
                mma16816(D[1][nt+1], ah[1], bh+2);
                mma16816(D[0][nt+1], ah[0], bl+2);
                mma16816(D[1][nt+1], ah[1], bl+2);
                mma16816(D[0][nt+1], al[0], bh+2);
                mma16816(D[1][nt+1], al[1], bh+2);
            }
        }
        __syncwarp();

        if (layer == 0) {
            const float* B2 = (const float*)(sm + S_B2);
            #pragma unroll
            for (int mt = 0; mt < 2; mt++) {
                int row0 = wm + mt*16 + g;
                #pragma unroll
                for (int nt = 0; nt < 8; nt++) {
                    int n0 = nt*8 + qc*2;
                    float v0 = fmaxf(D[mt][nt][0] + B2[n0],   0.f);
                    float v1 = fmaxf(D[mt][nt][1] + B2[n0+1], 0.f);
                    float v2 = fmaxf(D[mt][nt][2] + B2[n0],   0.f);
                    float v3 = fmaxf(D[mt][nt][3] + B2[n0+1], 0.f);
                    float h0,l0,h1,l1,h2,l2,h3,l3;
                    split2(v0,h0,l0); split2(v1,h1,l1); split2(v2,h2,l2); split2(v3,h3,l3);
                    *(u32*)(sm + S_AH + row0*144 + n0*2)     = pack_bf16x2(h0, h1);
                    *(u32*)(sm + S_AL + row0*144 + n0*2)     = pack_bf16x2(l0, l1);
                    *(u32*)(sm + S_AH + (row0+8)*144 + n0*2) = pack_bf16x2(h2, h3);
                    *(u32*)(sm + S_AL + (row0+8)*144 + n0*2) = pack_bf16x2(l2, l3);
                    D[mt][nt][0] = 0.f; D[mt][nt][1] = 0.f; D[mt][nt][2] = 0.f; D[mt][nt][3] = 0.f;
                }
            }
            __syncwarp();
        }
    }

    // ---- epilogue 3: out = relu(D + b3) . W4 + b4 ----
    {
        const float* B3 = (const float*)(sm + S_B3);
        const float* W4s = (const float*)(sm + S_W4);
        float b4v = b4[0];
        #pragma unroll
        for (int mt = 0; mt < 2; mt++) {
            float p0 = 0.f, p1 = 0.f;
            #pragma unroll
            for (int nt = 0; nt < 8; nt++) {
                int n0 = nt*8 + qc*2;
                p0 += fmaxf(D[mt][nt][0] + B3[n0],   0.f) * W4s[n0];
                p0 += fmaxf(D[mt][nt][1] + B3[n0+1], 0.f) * W4s[n0+1];
                p1 += fmaxf(D[mt][nt][2] + B3[n0],   0.f) * W4s[n0];
                p1 += fmaxf(D[mt][nt][3] + B3[n0+1], 0.f) * W4s[n0+1];
            }
            p0 += __shfl_xor_sync(0xffffffffu, p0, 1);
            p0 += __shfl_xor_sync(0xffffffffu, p0, 2);
            p1 += __shfl_xor_sync(0xffffffffu, p1, 1);
            p1 += __shfl_xor_sync(0xffffffffu, p1, 2);
            if (qc == 0) {
                out[ctaBase + wm + mt*16 + g]     = p0 + b4v;
                out[ctaBase + wm + mt*16 + g + 8] = p1 + b4v;
            }
        }
    }
}

extern "C" void kernel_launch(void* const* d_in, const int* in_sizes, int n_in,
                              void* d_out, int out_size) {
    const float* features = (const float*)d_in[0];
    const float* points   = (const float*)d_in[1];
    const float* kmat     = (const float*)d_in[2];
    const float* rtm      = (const float*)d_in[3];
    const float* Bg       = (const float*)d_in[4];
    const float* W1       = (const float*)d_in[5];
    const float* b1       = (const float*)d_in[6];
    const float* W2       = (const float*)d_in[7];
    const float* b2       = (const float*)d_in[8];
    const float* W3       = (const float*)d_in[9];
    const float* b3       = (const float*)d_in[10];
    const float* W4       = (const float*)d_in[11];
    const float* b4       = (const float*)d_in[12];

    transpose_kernel<<<BATCH * (PIX/32), 256>>>(features);
    prep_weights<<<96, 256>>>(W1, W2, W3);

    cudaFuncSetAttribute(decoder_kernel, cudaFuncAttributeMaxDynamicSharedMemorySize, SMEM_SZ);
    decoder_kernel<<<(BATCH*65536)/256, 256, SMEM_SZ>>>(
        points, kmat, rtm, Bg, b1, b2, b3, W4, b4, (float*)d_out);
}

// round 10
// speedup vs baseline: 4.2985x; 1.5063x over previous
#include <cuda_runtime.h>
#include <cuda_bf16.h>
#include <cstdint>

typedef uint32_t u32;

#define FDIM 128
#define HH 56
#define WW 56
#define BATCH 8
#define PIX (HH*WW)

// ---------------- global scratch ----------------
__device__ float g_feat[BATCH * PIX * FDIM];                 // (b,y,x,c)
__device__ __nv_bfloat16 g_w1t[2][64 * 264];                 // W1^T remapped, stride 264 hw
__device__ __nv_bfloat16 g_w2t[2][64 * 72];                  // W2^T, stride 72 hw
__device__ __nv_bfloat16 g_w3t[2][64 * 72];
// Pre-built per-lane B fragments (uint4 = 4 regs = 2 n-tiles)
__device__ uint4 g_f1[2][64][32];                            // [hl][(c*16)+(ks*4)+ntp][lane]
__device__ uint4 g_f2[2][16][32];                            // [hl][ks*4+ntp][lane]
__device__ uint4 g_f3[2][16][32];

// ---------------- transpose features ----------------
__global__ __launch_bounds__(256) void transpose_kernel(const float* __restrict__ feat) {
    int blk = blockIdx.x;
    int b = blk / 98;
    int pix0 = (blk % 98) * 32;
    __shared__ float tile[FDIM][33];
    int tx = threadIdx.x & 31;
    int ty = threadIdx.x >> 5;
    const float* src = feat + (size_t)b * FDIM * PIX;
    #pragma unroll
    for (int k = 0; k < 16; k++) {
        int c = ty + (k << 3);
        tile[c][tx] = src[c * PIX + pix0 + tx];
    }
    __syncthreads();
    int c2 = threadIdx.x & 127;
    int pg = threadIdx.x >> 7;
    float* dst = g_feat + ((size_t)b * PIX + pix0) * FDIM;
    #pragma unroll
    for (int p = pg; p < 32; p += 2) {
        dst[p * FDIM + c2] = tile[c2][p];
    }
}

// ---------------- weight prep ----------------
__global__ __launch_bounds__(256) void prep_weights(const float* __restrict__ W1,
                                                    const float* __restrict__ W2,
                                                    const float* __restrict__ W3) {
    int t = blockIdx.x * 256 + threadIdx.x;
    if (t < 16384) {                       // W1: [k=256][n=64] -> W1T[n][kk]
        int n = t >> 8, k = t & 255;
        int kk = (k < 128) ? k : (k < 192 ? 128 + 2 * (k - 128) : 129 + 2 * (k - 192));
        float w = W1[k * 64 + n];
        float h = __bfloat162float(__float2bfloat16(w));
        g_w1t[0][n * 264 + kk] = __float2bfloat16(h);
        g_w1t[1][n * 264 + kk] = __float2bfloat16(w - h);
    } else if (t < 16384 + 4096) {
        int i = t - 16384;
        int n = i >> 6, k = i & 63;
        float w = W2[k * 64 + n];
        float h = __bfloat162float(__float2bfloat16(w));
        g_w2t[0][n * 72 + k] = __float2bfloat16(h);
        g_w2t[1][n * 72 + k] = __float2bfloat16(w - h);
    } else if (t < 16384 + 8192) {
        int i = t - 20480;
        int n = i >> 6, k = i & 63;
        float w = W3[k * 64 + n];
        float h = __bfloat162float(__float2bfloat16(w));
        g_w3t[0][n * 72 + k] = __float2bfloat16(h);
        g_w3t[1][n * 72 + k] = __float2bfloat16(w - h);
    }
}

// ---------------- helpers ----------------
__device__ __forceinline__ u32 smem_u32(const void* p) {
    u32 a;
    asm("{ .reg .u64 t; cvta.to.shared.u64 t, %1; cvt.u32.u64 %0, t; }" : "=r"(a) : "l"(p));
    return a;
}
__device__ __forceinline__ u32 pack_bf16x2(float lo, float hi) {
    u32 r; asm("cvt.rn.bf16x2.f32 %0, %1, %2;" : "=r"(r) : "f"(hi), "f"(lo)); return r;
}
__device__ __forceinline__ void split2(float v, float& h, float& l) {
    h = __bfloat162float(__float2bfloat16(v));
    l = v - h;
}
__device__ __forceinline__ void ldx4(u32* r, u32 addr) {
    asm volatile("ldmatrix.sync.aligned.m8n8.x4.shared.b16 {%0,%1,%2,%3}, [%4];"
        : "=r"(r[0]), "=r"(r[1]), "=r"(r[2]), "=r"(r[3]) : "r"(addr));
}
__device__ __forceinline__ void mma16816(float* d, const u32* a, const u32* b) {
    asm volatile("mma.sync.aligned.m16n8k16.row.col.f32.bf16.bf16.f32 "
        "{%0,%1,%2,%3}, {%4,%5,%6,%7}, {%8,%9}, {%0,%1,%2,%3};"
        : "+f"(d[0]), "+f"(d[1]), "+f"(d[2]), "+f"(d[3])
        : "r"(a[0]), "r"(a[1]), "r"(a[2]), "r"(a[3]), "r"(b[0]), "r"(b[1]));
}

// ---------------- prep_frags: replay decoder's ldmatrix on staged weights ----------------
// staging smem layout (identical geometry to R8): W1 h @0 (528B rows), W1 l @33792,
// W2 h @67584 (144B rows), W2 l @76800, W3 h @86016, W3 l @95232. Total 104448B.
__global__ __launch_bounds__(256) void prep_frags() {
    extern __shared__ __align__(16) unsigned char psm[];
    const u32 pb = smem_u32(psm);
    const int tid = threadIdx.x;
    const int warp = tid >> 5;
    const int lane = tid & 31;
    {
        uint4* d4; const uint4* s4;
        d4 = (uint4*)(psm + 0);     s4 = (const uint4*)g_w1t[0];
        for (int i = tid; i < 2112; i += 256) d4[i] = s4[i];
        d4 = (uint4*)(psm + 33792); s4 = (const uint4*)g_w1t[1];
        for (int i = tid; i < 2112; i += 256) d4[i] = s4[i];
        d4 = (uint4*)(psm + 67584); s4 = (const uint4*)g_w2t[0];
        for (int i = tid; i < 576; i += 256) d4[i] = s4[i];
        d4 = (uint4*)(psm + 76800); s4 = (const uint4*)g_w2t[1];
        for (int i = tid; i < 576; i += 256) d4[i] = s4[i];
        d4 = (uint4*)(psm + 86016); s4 = (const uint4*)g_w3t[0];
        for (int i = tid; i < 576; i += 256) d4[i] = s4[i];
        d4 = (uint4*)(psm + 95232); s4 = (const uint4*)g_w3t[1];
        for (int i = tid; i < 576; i += 256) d4[i] = s4[i];
    }
    __syncthreads();

    u32 brow = (lane & 7) + ((lane >> 4) << 3);
    u32 khalf = ((lane >> 3) & 1) << 4;
    if (warp < 4) {                       // layer 1, chunk c = warp
        int c = warp;
        for (int ks = 0; ks < 4; ks++) {
            for (int ntp = 0; ntp < 4; ntp++) {
                u32 bk = c*128 + ks*32 + khalf;
                u32 baddr = (ntp*16 + brow) * 528 + bk;
                u32 bh[4], bl[4];
                ldx4(bh, pb + 0 + baddr);
                ldx4(bl, pb + 33792 + baddr);
                int idx = c*16 + ks*4 + ntp;
                g_f1[0][idx][lane] = make_uint4(bh[0], bh[1], bh[2], bh[3]);
                g_f1[1][idx][lane] = make_uint4(bl[0], bl[1], bl[2], bl[3]);
            }
        }
    } else if (warp == 4) {               // layer 2
        for (int ks = 0; ks < 4; ks++) {
            for (int ntp = 0; ntp < 4; ntp++) {
                u32 baddr = (ntp*16 + brow) * 144 + ks*32 + khalf;
                u32 bh[4], bl[4];
                ldx4(bh, pb + 67584 + baddr);
                ldx4(bl, pb + 76800 + baddr);
                int idx = ks*4 + ntp;
                g_f2[0][idx][lane] = make_uint4(bh[0], bh[1], bh[2], bh[3]);
                g_f2[1][idx][lane] = make_uint4(bl[0], bl[1], bl[2], bl[3]);
            }
        }
    } else if (warp == 5) {               // layer 3
        for (int ks = 0; ks < 4; ks++) {
            for (int ntp = 0; ntp < 4; ntp++) {
                u32 baddr = (ntp*16 + brow) * 144 + ks*32 + khalf;
                u32 bh[4], bl[4];
                ldx4(bh, pb + 86016 + baddr);
                ldx4(bl, pb + 95232 + baddr);
                int idx = ks*4 + ntp;
                g_f3[0][idx][lane] = make_uint4(bh[0], bh[1], bh[2], bh[3]);
                g_f3[1][idx][lane] = make_uint4(bl[0], bl[1], bl[2], bl[3]);
            }
        }
    }
}

// ---------------- decoder smem layout (bytes) ----------------
#define S_AH  0                 // 256 rows x 144B
#define S_AL  36864
#define S_B1  73728
#define S_B2  73984
#define S_B3  74240
#define S_W4  74496
#define S_PAR 74752             // 256 points x 32B
#define SMEM_SZ (74752 + 8192)  // 82944

__global__ __launch_bounds__(256, 2) void decoder_kernel(
    const float* __restrict__ points, const float* __restrict__ kmat,
    const float* __restrict__ rtm, const float* __restrict__ Bg,
    const float* __restrict__ b1, const float* __restrict__ b2,
    const float* __restrict__ b3, const float* __restrict__ W4,
    const float* __restrict__ b4, float* __restrict__ out)
{
    extern __shared__ __align__(16) unsigned char sm[];
    const u32 sbase = smem_u32(sm);
    const int tid = threadIdx.x;
    const int warp = tid >> 5;
    const int lane = tid & 31;

    if (tid < 64) {
        ((float*)(sm + S_B1))[tid] = b1[tid];
        ((float*)(sm + S_B2))[tid] = b2[tid];
        ((float*)(sm + S_B3))[tid] = b3[tid];
        ((float*)(sm + S_W4))[tid] = W4[tid];
    }

    // ---- projection: own point -> params table ----
    const int ctaBase = blockIdx.x * 256;
    const int pid = ctaBase + tid;
    const int b = pid >> 16;
    float px = points[pid*3+0], py = points[pid*3+1], pz = points[pid*3+2];
    {
        const float* rtb = rtm + b * 12;
        const float* kb = kmat + b * 9;
        float cx = rtb[0]*px + rtb[1]*py + rtb[2]*pz + rtb[3];
        float cy = rtb[4]*px + rtb[5]*py + rtb[6]*pz + rtb[7];
        float cz = rtb[8]*px + rtb[9]*py + rtb[10]*pz + rtb[11];
        float ix = kb[0]*cx + kb[1]*cy + kb[2]*cz;
        float iy = kb[3]*cx + kb[4]*cy + kb[5]*cz;
        float iz = kb[6]*cx + kb[7]*cy + kb[8]*cz;
        float zd = iz + 1e-8f;
        float u = ix / zd, v = iy / zd;
        float valid = (iz > 0.f) ? 1.f : 0.f;
        float un = (2.f*u + 1.f) / (float)WW - 1.f;
        float vn = (2.f*v + 1.f) / (float)HH - 1.f;
        float xs = ((un + 1.f) * (float)WW - 1.f) * 0.5f;
        float ys = ((vn + 1.f) * (float)HH - 1.f) * 0.5f;
        float x0f = floorf(xs), y0f = floorf(ys);
        float fx = xs - x0f, fy = ys - y0f;
        int x0 = (int)x0f, y0 = (int)y0f, x1 = x0 + 1, y1 = y0 + 1;
        float w00 = (1.f-fx)*(1.f-fy), w01 = fx*(1.f-fy), w10 = (1.f-fx)*fy, w11 = fx*fy;
        w00 *= ((x0>=0 && x0<WW && y0>=0 && y0<HH) ? valid : 0.f);
        w01 *= ((x1>=0 && x1<WW && y0>=0 && y0<HH) ? valid : 0.f);
        w10 *= ((x0>=0 && x0<WW && y1>=0 && y1<HH) ? valid : 0.f);
        w11 *= ((x1>=0 && x1<WW && y1>=0 && y1<HH) ? valid : 0.f);
        int x0c = min(max(x0,0),WW-1), x1c = min(max(x1,0),WW-1);
        int y0c = min(max(y0,0),HH-1), y1c = min(max(y1,0),HH-1);
        int4* pi = (int4*)(sm + S_PAR + tid*32);
        float4* pf = (float4*)(sm + S_PAR + tid*32 + 16);
        *pi = make_int4(((b*HH + y0c)*WW + x0c) * 32, ((b*HH + y0c)*WW + x1c) * 32,
                        ((b*HH + y1c)*WW + x0c) * 32, ((b*HH + y1c)*WW + x1c) * 32);
        *pf = make_float4(w00, w01, w10, w11);
    }
    __syncthreads();   // only CTA barrier

    // ---- layer-1: 4 K-chunks of 64 ----
    const int wm = warp * 32;
    float D[2][8][4];
    #pragma unroll
    for (int mt = 0; mt < 2; mt++)
        #pragma unroll
        for (int nt = 0; nt < 8; nt++)
            #pragma unroll
            for (int q = 0; q < 4; q++) D[mt][nt][q] = 0.f;

    const float4* g4 = (const float4*)g_feat;
    const float TWO_PI = 6.283185307179586f;
    const int half = lane >> 4;
    const int slot = lane & 15;

    #pragma unroll 1
    for (int c = 0; c < 4; c++) {
        if (c < 2) {
            #pragma unroll 2
            for (int pp = 0; pp < 32; pp += 2) {
                int t = wm + pp + half;
                const int4 ci = *(const int4*)(sm + S_PAR + t*32);
                const float4 cw = *(const float4*)(sm + S_PAR + t*32 + 16);
                int c4 = c * 16 + slot;
                float4 A = g4[ci.x + c4];
                float4 B = g4[ci.y + c4];
                float4 C = g4[ci.z + c4];
                float4 E = g4[ci.w + c4];
                float f0 = cw.x*A.x + cw.y*B.x + cw.z*C.x + cw.w*E.x;
                float f1 = cw.x*A.y + cw.y*B.y + cw.z*C.y + cw.w*E.y;
                float f2 = cw.x*A.z + cw.y*B.z + cw.z*C.z + cw.w*E.z;
                float f3 = cw.x*A.w + cw.y*B.w + cw.z*C.w + cw.w*E.w;
                float h0,l0,h1,l1,h2,l2,h3,l3;
                split2(f0,h0,l0); split2(f1,h1,l1); split2(f2,h2,l2); split2(f3,h3,l3);
                u32* dh = (u32*)(sm + S_AH + t*144 + slot*8);
                u32* dl = (u32*)(sm + S_AL + t*144 + slot*8);
                dh[0] = pack_bf16x2(h0, h1); dh[1] = pack_bf16x2(h2, h3);
                dl[0] = pack_bf16x2(l0, l1); dl[1] = pack_bf16x2(l2, l3);
            }
        } else {
            int mbase = (c - 2) * 32;
            #pragma unroll
            for (int q = 0; q < 16; q++) {
                int m = mbase + 2 * q;
                float a0 = TWO_PI * (px*__ldg(Bg+3*m)   + py*__ldg(Bg+3*m+1) + pz*__ldg(Bg+3*m+2));
                float a1 = TWO_PI * (px*__ldg(Bg+3*m+3) + py*__ldg(Bg+3*m+4) + pz*__ldg(Bg+3*m+5));
                float s0, cc0, s1, cc1;
                __sincosf(a0, &s0, &cc0);
                __sincosf(a1, &s1, &cc1);
                float h0,l0,h1,l1,h2,l2,h3,l3;
                split2(s0,h0,l0); split2(cc0,h1,l1); split2(s1,h2,l2); split2(cc1,h3,l3);
                u32* dh = (u32*)(sm + S_AH + tid*144 + q*8);
                u32* dl = (u32*)(sm + S_AL + tid*144 + q*8);
                dh[0] = pack_bf16x2(h0, h1); dh[1] = pack_bf16x2(h2, h3);
                dl[0] = pack_bf16x2(l0, l1); dl[1] = pack_bf16x2(l2, l3);
            }
        }
        __syncwarp();

        #pragma unroll
        for (int ks = 0; ks < 4; ks++) {
            int k0b = ks * 32;
            u32 ah[2][4], al[2][4];
            u32 arow = wm + (lane & 15);
            u32 akb = k0b + ((lane >> 4) << 4);
            ldx4(ah[0], sbase + S_AH + arow*144 + akb);
            ldx4(al[0], sbase + S_AL + arow*144 + akb);
            ldx4(ah[1], sbase + S_AH + (arow+16)*144 + akb);
            ldx4(al[1], sbase + S_AL + (arow+16)*144 + akb);
            #pragma unroll
            for (int ntp = 0; ntp < 4; ntp++) {
                int idx = c*16 + ks*4 + ntp;
                uint4 vh = g_f1[0][idx][lane];
                uint4 vl = g_f1[1][idx][lane];
                u32 bh[4] = {vh.x, vh.y, vh.z, vh.w};
                u32 bl[4] = {vl.x, vl.y, vl.z, vl.w};
                int nt = 2 * ntp;
                mma16816(D[0][nt],   ah[0], bh+0);
                mma16816(D[1][nt],   ah[1], bh+0);
                mma16816(D[0][nt],   ah[0], bl+0);
                mma16816(D[1][nt],   ah[1], bl+0);
                mma16816(D[0][nt],   al[0], bh+0);
                mma16816(D[1][nt],   al[1], bh+0);
                mma16816(D[0][nt+1], ah[0], bh+2);
                mma16816(D[1][nt+1], ah[1], bh+2);
                mma16816(D[0][nt+1], ah[0], bl+2);
                mma16816(D[1][nt+1], ah[1], bl+2);
                mma16816(D[0][nt+1], al[0], bh+2);
                mma16816(D[1][nt+1], al[1], bh+2);
            }
        }
        __syncwarp();
    }

    const int g = lane >> 2;
    const int qc = lane & 3;

    // ---- epilogue 1 ----
    {
        const float* B1 = (const float*)(sm + S_B1);
        #pragma unroll
        for (int mt = 0; mt < 2; mt++) {
            int row0 = wm + mt*16 + g;
            #pragma unroll
            for (int nt = 0; nt < 8; nt++) {
                int n0 = nt*8 + qc*2;
                float v0 = fmaxf(D[mt][nt][0] + B1[n0],   0.f);
                float v1 = fmaxf(D[mt][nt][1] + B1[n0+1], 0.f);
                float v2 = fmaxf(D[mt][nt][2] + B1[n0],   0.f);
                float v3 = fmaxf(D[mt][nt][3] + B1[n0+1], 0.f);
                float h0,l0,h1,l1,h2,l2,h3,l3;
                split2(v0,h0,l0); split2(v1,h1,l1); split2(v2,h2,l2); split2(v3,h3,l3);
                *(u32*)(sm + S_AH + row0*144 + n0*2)     = pack_bf16x2(h0, h1);
                *(u32*)(sm + S_AL + row0*144 + n0*2)     = pack_bf16x2(l0, l1);
                *(u32*)(sm + S_AH + (row0+8)*144 + n0*2) = pack_bf16x2(h2, h3);
                *(u32*)(sm + S_AL + (row0+8)*144 + n0*2) = pack_bf16x2(l2, l3);
                D[mt][nt][0] = 0.f; D[mt][nt][1] = 0.f; D[mt][nt][2] = 0.f; D[mt][nt][3] = 0.f;
            }
        }
    }
    __syncwarp();

    // ---- layers 2 and 3 ----
    #pragma unroll 1
    for (int layer = 0; layer < 2; layer++) {
        #pragma unroll
        for (int ks = 0; ks < 4; ks++) {
            int k0b = ks * 32;
            u32 ah[2][4], al[2][4];
            u32 arow = wm + (lane & 15);
            u32 akb = k0b + ((lane >> 4) << 4);
            ldx4(ah[0], sbase + S_AH + arow*144 + akb);
            ldx4(al[0], sbase + S_AL + arow*144 + akb);
            ldx4(ah[1], sbase + S_AH + (arow+16)*144 + akb);
            ldx4(al[1], sbase + S_AL + (arow+16)*144 + akb);
            #pragma unroll
            for (int ntp = 0; ntp < 4; ntp++) {
                int idx = ks*4 + ntp;
                uint4 vh = layer == 0 ? g_f2[0][idx][lane] : g_f3[0][idx][lane];
                uint4 vl = layer == 0 ? g_f2[1][idx][lane] : g_f3[1][idx][lane];
                u32 bh[4] = {vh.x, vh.y, vh.z, vh.w};
                u32 bl[4] = {vl.x, vl.y, vl.z, vl.w};
                int nt = 2 * ntp;
                mma16816(D[0][nt],   ah[0], bh+0);
                mma16816(D[1][nt],   ah[1], bh+0);
                mma16816(D[0][nt],   ah[0], bl+0);
                mma16816(D[1][nt],   ah[1], bl+0);
                mma16816(D[0][nt],   al[0], bh+0);
                mma16816(D[1][nt],   al[1], bh+0);
                mma16816(D[0][nt+1], ah[0], bh+2);
                mma16816(D[1][nt+1], ah[1], bh+2);
                mma16816(D[0][nt+1], ah[0], bl+2);
                mma16816(D[1][nt+1], ah[1], bl+2);
                mma16816(D[0][nt+1], al[0], bh+2);
                mma16816(D[1][nt+1], al[1], bh+2);
            }
        }
        __syncwarp();

        if (layer == 0) {
            const float* B2 = (const float*)(sm + S_B2);
            #pragma unroll
            for (int mt = 0; mt < 2; mt++) {
                int row0 = wm + mt*16 + g;
                #pragma unroll
                for (int nt = 0; nt < 8; nt++) {
                    int n0 = nt*8 + qc*2;
                    float v0 = fmaxf(D[mt][nt][0] + B2[n0],   0.f);
                    float v1 = fmaxf(D[mt][nt][1] + B2[n0+1], 0.f);
                    float v2 = fmaxf(D[mt][nt][2] + B2[n0],   0.f);
                    float v3 = fmaxf(D[mt][nt][3] + B2[n0+1], 0.f);
                    float h0,l0,h1,l1,h2,l2,h3,l3;
                    split2(v0,h0,l0); split2(v1,h1,l1); split2(v2,h2,l2); split2(v3,h3,l3);
                    *(u32*)(sm + S_AH + row0*144 + n0*2)     = pack_bf16x2(h0, h1);
                    *(u32*)(sm + S_AL + row0*144 + n0*2)     = pack_bf16x2(l0, l1);
                    *(u32*)(sm + S_AH + (row0+8)*144 + n0*2) = pack_bf16x2(h2, h3);
                    *(u32*)(sm + S_AL + (row0+8)*144 + n0*2) = pack_bf16x2(l2, l3);
                    D[mt][nt][0] = 0.f; D[mt][nt][1] = 0.f; D[mt][nt][2] = 0.f; D[mt][nt][3] = 0.f;
                }
            }
            __syncwarp();
        }
    }

    // ---- epilogue 3: out = relu(D + b3) . W4 + b4 ----
    {
        const float* B3 = (const float*)(sm + S_B3);
        const float* W4s = (const float*)(sm + S_W4);
        float b4v = b4[0];
        #pragma unroll
        for (int mt = 0; mt < 2; mt++) {
            float p0 = 0.f, p1 = 0.f;
            #pragma unroll
            for (int nt = 0; nt < 8; nt++) {
                int n0 = nt*8 + qc*2;
                p0 += fmaxf(D[mt][nt][0] + B3[n0],   0.f) * W4s[n0];
                p0 += fmaxf(D[mt][nt][1] + B3[n0+1], 0.f) * W4s[n0+1];
                p1 += fmaxf(D[mt][nt][2] + B3[n0],   0.f) * W4s[n0];
                p1 += fmaxf(D[mt][nt][3] + B3[n0+1], 0.f) * W4s[n0+1];
            }
            p0 += __shfl_xor_sync(0xffffffffu, p0, 1);
            p0 += __shfl_xor_sync(0xffffffffu, p0, 2);
            p1 += __shfl_xor_sync(0xffffffffu, p1, 1);
            p1 += __shfl_xor_sync(0xffffffffu, p1, 2);
            if (qc == 0) {
                out[ctaBase + wm + mt*16 + g]     = p0 + b4v;
                out[ctaBase + wm + mt*16 + g + 8] = p1 + b4v;
            }
        }
    }
}

extern "C" void kernel_launch(void* const* d_in, const int* in_sizes, int n_in,
                              void* d_out, int out_size) {
    const float* features = (const float*)d_in[0];
    const float* points   = (const float*)d_in[1];
    const float* kmat     = (const float*)d_in[2];
    const float* rtm      = (const float*)d_in[3];
    const float* Bg       = (const float*)d_in[4];
    const float* W1       = (const float*)d_in[5];
    const float* b1       = (const float*)d_in[6];
    const float* W2       = (const float*)d_in[7];
    const float* b2       = (const float*)d_in[8];
    const float* W3       = (const float*)d_in[9];
    const float* b3       = (const float*)d_in[10];
    const float* W4       = (const float*)d_in[11];
    const float* b4       = (const float*)d_in[12];

    transpose_kernel<<<BATCH * (PIX/32), 256>>>(features);
    prep_weights<<<96, 256>>>(W1, W2, W3);
    cudaFuncSetAttribute(prep_frags, cudaFuncAttributeMaxDynamicSharedMemorySize, 104448);
    prep_frags<<<1, 256, 104448>>>();

    cudaFuncSetAttribute(decoder_kernel, cudaFuncAttributeMaxDynamicSharedMemorySize, SMEM_SZ);
    decoder_kernel<<<(BATCH*65536)/256, 256, SMEM_SZ>>>(
        points, kmat, rtm, Bg, b1, b2, b3, W4, b4, (float*)d_out);
}

// round 15
// speedup vs baseline: 5.4287x; 1.2629x over previous
#include <cuda_runtime.h>
#include <cuda_fp16.h>
#include <cstdint>

typedef uint32_t u32;

#define FDIM 128
#define HH 56
#define WW 56
#define BATCH 8
#define PIX (HH*WW)

// ---------------- global scratch ----------------
__device__ float g_feat[BATCH * PIX * FDIM];                 // (b,y,x,c)
__device__ __half g_w1t[64 * 264];                           // W1^T remapped (fp16), stride 264 hw
__device__ __half g_w2t[64 * 72];                            // W2^T, stride 72 hw
__device__ __half g_w3t[64 * 72];
// Pre-built per-lane B fragments (uint4 = 4 regs = 2 n-tiles)
__device__ uint4 g_f1[64][32];                               // [(c*16)+(ks*4)+ntp][lane]
__device__ uint4 g_f2[16][32];                               // [ks*4+ntp][lane]
__device__ uint4 g_f3[16][32];

// ---------------- transpose features ----------------
__global__ __launch_bounds__(256) void transpose_kernel(const float* __restrict__ feat) {
    int blk = blockIdx.x;
    int b = blk / 98;
    int pix0 = (blk % 98) * 32;
    __shared__ float tile[FDIM][33];
    int tx = threadIdx.x & 31;
    int ty = threadIdx.x >> 5;
    const float* src = feat + (size_t)b * FDIM * PIX;
    #pragma unroll
    for (int k = 0; k < 16; k++) {
        int c = ty + (k << 3);
        tile[c][tx] = src[c * PIX + pix0 + tx];
    }
    __syncthreads();
    int c2 = threadIdx.x & 127;
    int pg = threadIdx.x >> 7;
    float* dst = g_feat + ((size_t)b * PIX + pix0) * FDIM;
    #pragma unroll
    for (int p = pg; p < 32; p += 2) {
        dst[p * FDIM + c2] = tile[c2][p];
    }
}

// ---------------- weight prep (fp16, hi only) ----------------
__global__ __launch_bounds__(256) void prep_weights(const float* __restrict__ W1,
                                                    const float* __restrict__ W2,
                                                    const float* __restrict__ W3) {
    int t = blockIdx.x * 256 + threadIdx.x;
    if (t < 16384) {                       // W1: [k=256][n=64] -> W1T[n][kk]
        int n = t >> 8, k = t & 255;
        int kk = (k < 128) ? k : (k < 192 ? 128 + 2 * (k - 128) : 129 + 2 * (k - 192));
        g_w1t[n * 264 + kk] = __float2half_rn(W1[k * 64 + n]);
    } else if (t < 16384 + 4096) {
        int i = t - 16384;
        int n = i >> 6, k = i & 63;
        g_w2t[n * 72 + k] = __float2half_rn(W2[k * 64 + n]);
    } else if (t < 16384 + 8192) {
        int i = t - 20480;
        int n = i >> 6, k = i & 63;
        g_w3t[n * 72 + k] = __float2half_rn(W3[k * 64 + n]);
    }
}

// ---------------- helpers ----------------
__device__ __forceinline__ u32 smem_u32(const void* p) {
    u32 a;
    asm("{ .reg .u64 t; cvta.to.shared.u64 t, %1; cvt.u32.u64 %0, t; }" : "=r"(a) : "l"(p));
    return a;
}
__device__ __forceinline__ u32 pack_f16x2(float lo, float hi) {  // low hw = lo
    u32 r; asm("cvt.rn.f16x2.f32 %0, %1, %2;" : "=r"(r) : "f"(hi), "f"(lo)); return r;
}
__device__ __forceinline__ void split2(float v, float& h, float& l) {
    h = __half2float(__float2half_rn(v));
    l = v - h;
}
__device__ __forceinline__ void ldx4(u32* r, u32 addr) {
    asm volatile("ldmatrix.sync.aligned.m8n8.x4.shared.b16 {%0,%1,%2,%3}, [%4];"
        : "=r"(r[0]), "=r"(r[1]), "=r"(r[2]), "=r"(r[3]) : "r"(addr));
}
__device__ __forceinline__ void mma16816(float* d, const u32* a, const u32* b) {
    asm volatile("mma.sync.aligned.m16n8k16.row.col.f32.f16.f16.f32 "
        "{%0,%1,%2,%3}, {%4,%5,%6,%7}, {%8,%9}, {%0,%1,%2,%3};"
        : "+f"(d[0]), "+f"(d[1]), "+f"(d[2]), "+f"(d[3])
        : "r"(a[0]), "r"(a[1]), "r"(a[2]), "r"(a[3]), "r"(b[0]), "r"(b[1]));
}

// ---------------- prep_frags: replay decoder's ldmatrix on staged weights ----------------
// staging smem: W1 @0 (528B rows, 33792B), W2 @33792 (144B rows, 9216B), W3 @43008 (9216B)
__global__ __launch_bounds__(256) void prep_frags() {
    extern __shared__ __align__(16) unsigned char psm[];
    const u32 pb = smem_u32(psm);
    const int tid = threadIdx.x;
    const int warp = tid >> 5;
    const int lane = tid & 31;
    {
        uint4* d4; const uint4* s4;
        d4 = (uint4*)(psm + 0);     s4 = (const uint4*)g_w1t;
        for (int i = tid; i < 2112; i += 256) d4[i] = s4[i];
        d4 = (uint4*)(psm + 33792); s4 = (const uint4*)g_w2t;
        for (int i = tid; i < 576; i += 256) d4[i] = s4[i];
        d4 = (uint4*)(psm + 43008); s4 = (const uint4*)g_w3t;
        for (int i = tid; i < 576; i += 256) d4[i] = s4[i];
    }
    __syncthreads();

    u32 brow = (lane & 7) + ((lane >> 4) << 3);
    u32 khalf = ((lane >> 3) & 1) << 4;
    if (warp < 4) {                       // layer 1, chunk c = warp
        int c = warp;
        for (int ks = 0; ks < 4; ks++) {
            for (int ntp = 0; ntp < 4; ntp++) {
                u32 bk = c*128 + ks*32 + khalf;
                u32 baddr = (ntp*16 + brow) * 528 + bk;
                u32 bh[4];
                ldx4(bh, pb + 0 + baddr);
                g_f1[c*16 + ks*4 + ntp][lane] = make_uint4(bh[0], bh[1], bh[2], bh[3]);
            }
        }
    } else if (warp == 4) {               // layer 2
        for (int ks = 0; ks < 4; ks++) {
            for (int ntp = 0; ntp < 4; ntp++) {
                u32 baddr = (ntp*16 + brow) * 144 + ks*32 + khalf;
                u32 bh[4];
                ldx4(bh, pb + 33792 + baddr);
                g_f2[ks*4 + ntp][lane] = make_uint4(bh[0], bh[1], bh[2], bh[3]);
            }
        }
    } else if (warp == 5) {               // layer 3
        for (int ks = 0; ks < 4; ks++) {
            for (int ntp = 0; ntp < 4; ntp++) {
                u32 baddr = (ntp*16 + brow) * 144 + ks*32 + khalf;
                u32 bh[4];
                ldx4(bh, pb + 43008 + baddr);
                g_f3[ks*4 + ntp][lane] = make_uint4(bh[0], bh[1], bh[2], bh[3]);
            }
        }
    }
}

// ---------------- decoder smem layout (bytes) ----------------
#define S_AH  0                 // 256 rows x 144B
#define S_AL  36864
#define S_B1  73728
#define S_B2  73984
#define S_B3  74240
#define S_W4  74496
#define S_PAR 74752             // 256 points x 32B
#define SMEM_SZ (74752 + 8192)  // 82944

__global__ __launch_bounds__(256, 2) void decoder_kernel(
    const float* __restrict__ points, const float* __restrict__ kmat,
    const float* __restrict__ rtm, const float* __restrict__ Bg,
    const float* __restrict__ b1, const float* __restrict__ b2,
    const float* __restrict__ b3, const float* __restrict__ W4,
    const float* __restrict__ b4, float* __restrict__ out)
{
    extern __shared__ __align__(16) unsigned char sm[];
    const u32 sbase = smem_u32(sm);
    const int tid = threadIdx.x;
    const int warp = tid >> 5;
    const int lane = tid & 31;

    if (tid < 64) {
        ((float*)(sm + S_B1))[tid] = b1[tid];
        ((float*)(sm + S_B2))[tid] = b2[tid];
        ((float*)(sm + S_B3))[tid] = b3[tid];
        ((float*)(sm + S_W4))[tid] = W4[tid];
    }

    // ---- projection: own point -> params table ----
    const int ctaBase = blockIdx.x * 256;
    const int pid = ctaBase + tid;
    const int b = pid >> 16;
    float px = points[pid*3+0], py = points[pid*3+1], pz = points[pid*3+2];
    {
        const float* rtb = rtm + b * 12;
        const float* kb = kmat + b * 9;
        float cx = rtb[0]*px + rtb[1]*py + rtb[2]*pz + rtb[3];
        float cy = rtb[4]*px + rtb[5]*py + rtb[6]*pz + rtb[7];
        float cz = rtb[8]*px + rtb[9]*py + rtb[10]*pz + rtb[11];
        float ix = kb[0]*cx + kb[1]*cy + kb[2]*cz;
        float iy = kb[3]*cx + kb[4]*cy + kb[5]*cz;
        float iz = kb[6]*cx + kb[7]*cy + kb[8]*cz;
        float zd = iz + 1e-8f;
        float u = ix / zd, v = iy / zd;
        float valid = (iz > 0.f) ? 1.f : 0.f;
        float un = (2.f*u + 1.f) / (float)WW - 1.f;
        float vn = (2.f*v + 1.f) / (float)HH - 1.f;
        float xs = ((un + 1.f) * (float)WW - 1.f) * 0.5f;
        float ys = ((vn + 1.f) * (float)HH - 1.f) * 0.5f;
        float x0f = floorf(xs), y0f = floorf(ys);
        float fx = xs - x0f, fy = ys - y0f;
        int x0 = (int)x0f, y0 = (int)y0f, x1 = x0 + 1, y1 = y0 + 1;
        float w00 = (1.f-fx)*(1.f-fy), w01 = fx*(1.f-fy), w10 = (1.f-fx)*fy, w11 = fx*fy;
        w00 *= ((x0>=0 && x0<WW && y0>=0 && y0<HH) ? valid : 0.f);
        w01 *= ((x1>=0 && x1<WW && y0>=0 && y0<HH) ? valid : 0.f);
        w10 *= ((x0>=0 && x0<WW && y1>=0 && y1<HH) ? valid : 0.f);
        w11 *= ((x1>=0 && x1<WW && y1>=0 && y1<HH) ? valid : 0.f);
        int x0c = min(max(x0,0),WW-1), x1c = min(max(x1,0),WW-1);
        int y0c = min(max(y0,0),HH-1), y1c = min(max(y1,0),HH-1);
        int4* pi = (int4*)(sm + S_PAR + tid*32);
        float4* pf = (float4*)(sm + S_PAR + tid*32 + 16);
        *pi = make_int4(((b*HH + y0c)*WW + x0c) * 32, ((b*HH + y0c)*WW + x1c) * 32,
                        ((b*HH + y1c)*WW + x0c) * 32, ((b*HH + y1c)*WW + x1c) * 32);
        *pf = make_float4(w00, w01, w10, w11);
    }
    __syncthreads();   // only CTA barrier

    // ---- layer-1: 4 K-chunks of 64 ----
    const int wm = warp * 32;
    float D[2][8][4];
    #pragma unroll
    for (int mt = 0; mt < 2; mt++)
        #pragma unroll
        for (int nt = 0; nt < 8; nt++)
            #pragma unroll
            for (int q = 0; q < 4; q++) D[mt][nt][q] = 0.f;

    const float4* g4 = (const float4*)g_feat;
    const float TWO_PI = 6.283185307179586f;
    const int half = lane >> 4;
    const int slot = lane & 15;

    #pragma unroll 1
    for (int c = 0; c < 4; c++) {
        if (c < 2) {
            #pragma unroll 2
            for (int pp = 0; pp < 32; pp += 2) {
                int t = wm + pp + half;
                const int4 ci = *(const int4*)(sm + S_PAR + t*32);
                const float4 cw = *(const float4*)(sm + S_PAR + t*32 + 16);
                int c4 = c * 16 + slot;
                float4 A = g4[ci.x + c4];
                float4 B = g4[ci.y + c4];
                float4 C = g4[ci.z + c4];
                float4 E = g4[ci.w + c4];
                float f0 = cw.x*A.x + cw.y*B.x + cw.z*C.x + cw.w*E.x;
                float f1 = cw.x*A.y + cw.y*B.y + cw.z*C.y + cw.w*E.y;
                float f2 = cw.x*A.z + cw.y*B.z + cw.z*C.z + cw.w*E.z;
                float f3 = cw.x*A.w + cw.y*B.w + cw.z*C.w + cw.w*E.w;
                float h0,l0,h1,l1,h2,l2,h3,l3;
                split2(f0,h0,l0); split2(f1,h1,l1); split2(f2,h2,l2); split2(f3,h3,l3);
                u32* dh = (u32*)(sm + S_AH + t*144 + slot*8);
                u32* dl = (u32*)(sm + S_AL + t*144 + slot*8);
                dh[0] = pack_f16x2(h0, h1); dh[1] = pack_f16x2(h2, h3);
                dl[0] = pack_f16x2(l0, l1); dl[1] = pack_f16x2(l2, l3);
            }
        } else {
            int mbase = (c - 2) * 32;
            #pragma unroll
            for (int q = 0; q < 16; q++) {
                int m = mbase + 2 * q;
                float a0 = TWO_PI * (px*__ldg(Bg+3*m)   + py*__ldg(Bg+3*m+1) + pz*__ldg(Bg+3*m+2));
                float a1 = TWO_PI * (px*__ldg(Bg+3*m+3) + py*__ldg(Bg+3*m+4) + pz*__ldg(Bg+3*m+5));
                float s0, cc0, s1, cc1;
                __sincosf(a0, &s0, &cc0);
                __sincosf(a1, &s1, &cc1);
                float h0,l0,h1,l1,h2,l2,h3,l3;
                split2(s0,h0,l0); split2(cc0,h1,l1); split2(s1,h2,l2); split2(cc1,h3,l3);
                u32* dh = (u32*)(sm + S_AH + tid*144 + q*8);
                u32* dl = (u32*)(sm + S_AL + tid*144 + q*8);
                dh[0] = pack_f16x2(h0, h1); dh[1] = pack_f16x2(h2, h3);
                dl[0] = pack_f16x2(l0, l1); dl[1] = pack_f16x2(l2, l3);
            }
        }
        __syncwarp();

        #pragma unroll
        for (int ks = 0; ks < 4; ks++) {
            int k0b = ks * 32;
            u32 ah[2][4], al[2][4];
            u32 arow = wm + (lane & 15);
            u32 akb = k0b + ((lane >> 4) << 4);
            ldx4(ah[0], sbase + S_AH + arow*144 + akb);
            ldx4(al[0], sbase + S_AL + arow*144 + akb);
            ldx4(ah[1], sbase + S_AH + (arow+16)*144 + akb);
            ldx4(al[1], sbase + S_AL + (arow+16)*144 + akb);
            #pragma unroll
            for (int ntp = 0; ntp < 4; ntp++) {
                int idx = c*16 + ks*4 + ntp;
                uint4 vh = g_f1[idx][lane];
                u32 bh[4] = {vh.x, vh.y, vh.z, vh.w};
                int nt = 2 * ntp;
                mma16816(D[0][nt],   ah[0], bh+0);
                mma16816(D[1][nt],   ah[1], bh+0);
                mma16816(D[0][nt],   al[0], bh+0);
                mma16816(D[1][nt],   al[1], bh+0);
                mma16816(D[0][nt+1], ah[0], bh+2);
                mma16816(D[1][nt+1], ah[1], bh+2);
                mma16816(D[0][nt+1], al[0], bh+2);
                mma16816(D[1][nt+1], al[1], bh+2);
            }
        }
        __syncwarp();
    }

    const int g = lane >> 2;
    const int qc = lane & 3;

    // ---- epilogue 1 ----
    {
        const float* B1 = (const float*)(sm + S_B1);
        #pragma unroll
        for (int mt = 0; mt < 2; mt++) {
            int row0 = wm + mt*16 + g;
            #pragma unroll
            for (int nt = 0; nt < 8; nt++) {
                int n0 = nt*8 + qc*2;
                float v0 = fmaxf(D[mt][nt][0] + B1[n0],   0.f);
                float v1 = fmaxf(D[mt][nt][1] + B1[n0+1], 0.f);
                float v2 = fmaxf(D[mt][nt][2] + B1[n0],   0.f);
                float v3 = fmaxf(D[mt][nt][3] + B1[n0+1], 0.f);
                float h0,l0,h1,l1,h2,l2,h3,l3;
                split2(v0,h0,l0); split2(v1,h1,l1); split2(v2,h2,l2); split2(v3,h3,l3);
                *(u32*)(sm + S_AH + row0*144 + n0*2)     = pack_f16x2(h0, h1);
                *(u32*)(sm + S_AL + row0*144 + n0*2)     = pack_f16x2(l0, l1);
                *(u32*)(sm + S_AH + (row0+8)*144 + n0*2) = pack_f16x2(h2, h3);
                *(u32*)(sm + S_AL + (row0+8)*144 + n0*2) = pack_f16x2(l2, l3);
                D[mt][nt][0] = 0.f; D[mt][nt][1] = 0.f; D[mt][nt][2] = 0.f; D[mt][nt][3] = 0.f;
            }
        }
    }
    __syncwarp();

    // ---- layers 2 and 3 ----
    #pragma unroll 1
    for (int layer = 0; layer < 2; layer++) {
        #pragma unroll
        for (int ks = 0; ks < 4; ks++) {
            int k0b = ks * 32;
            u32 ah[2][4], al[2][4];
            u32 arow = wm + (lane & 15);
            u32 akb = k0b + ((lane >> 4) << 4);
            ldx4(ah[0], sbase + S_AH + arow*144 + akb);
            ldx4(al[0], sbase + S_AL + arow*144 + akb);
            ldx4(ah[1], sbase + S_AH + (arow+16)*144 + akb);
            ldx4(al[1], sbase + S_AL + (arow+16)*144 + akb);
            #pragma unroll
            for (int ntp = 0; ntp < 4; ntp++) {
                int idx = ks*4 + ntp;
                uint4 vh = layer == 0 ? g_f2[idx][lane] : g_f3[idx][lane];
                u32 bh[4] = {vh.x, vh.y, vh.z, vh.w};
                int nt = 2 * ntp;
                mma16816(D[0][nt],   ah[0], bh+0);
                mma16816(D[1][nt],   ah[1], bh+0);
                mma16816(D[0][nt],   al[0], bh+0);
                mma16816(D[1][nt],   al[1], bh+0);
                mma16816(D[0][nt+1], ah[0], bh+2);
                mma16816(D[1][nt+1], ah[1], bh+2);
                mma16816(D[0][nt+1], al[0], bh+2);
                mma16816(D[1][nt+1], al[1], bh+2);
            }
        }
        __syncwarp();

        if (layer == 0) {
            const float* B2 = (const float*)(sm + S_B2);
            #pragma unroll
            for (int mt = 0; mt < 2; mt++) {
                int row0 = wm + mt*16 + g;
                #pragma unroll
                for (int nt = 0; nt < 8; nt++) {
                    int n0 = nt*8 + qc*2;
                    float v0 = fmaxf(D[mt][nt][0] + B2[n0],   0.f);
                    float v1 = fmaxf(D[mt][nt][1] + B2[n0+1], 0.f);
                    float v2 = fmaxf(D[mt][nt][2] + B2[n0],   0.f);
                    float v3 = fmaxf(D[mt][nt][3] + B2[n0+1], 0.f);
                    float h0,l0,h1,l1,h2,l2,h3,l3;
                    split2(v0,h0,l0); split2(v1,h1,l1); split2(v2,h2,l2); split2(v3,h3,l3);
                    *(u32*)(sm + S_AH + row0*144 + n0*2)     = pack_f16x2(h0, h1);
                    *(u32*)(sm + S_AL + row0*144 + n0*2)     = pack_f16x2(l0, l1);
                    *(u32*)(sm + S_AH + (row0+8)*144 + n0*2) = pack_f16x2(h2, h3);
                    *(u32*)(sm + S_AL + (row0+8)*144 + n0*2) = pack_f16x2(l2, l3);
                    D[mt][nt][0] = 0.f; D[mt][nt][1] = 0.f; D[mt][nt][2] = 0.f; D[mt][nt][3] = 0.f;
                }
            }
            __syncwarp();
        }
    }

    // ---- epilogue 3: out = relu(D + b3) . W4 + b4 ----
    {
        const float* B3 = (const float*)(sm + S_B3);
        const float* W4s = (const float*)(sm + S_W4);
        float b4v = b4[0];
        #pragma unroll
        for (int mt = 0; mt < 2; mt++) {
            float p0 = 0.f, p1 = 0.f;
            #pragma unroll
            for (int nt = 0; nt < 8; nt++) {
                int n0 = nt*8 + qc*2;
                p0 += fmaxf(D[mt][nt][0] + B3[n0],   0.f) * W4s[n0];
                p0 += fmaxf(D[mt][nt][1] + B3[n0+1], 0.f) * W4s[n0+1];
                p1 += fmaxf(D[mt][nt][2] + B3[n0],   0.f) * W4s[n0];
                p1 += fmaxf(D[mt][nt][3] + B3[n0+1], 0.f) * W4s[n0+1];
            }
            p0 += __shfl_xor_sync(0xffffffffu, p0, 1);
            p0 += __shfl_xor_sync(0xffffffffu, p0, 2);
            p1 += __shfl_xor_sync(0xffffffffu, p1, 1);
            p1 += __shfl_xor_sync(0xffffffffu, p1, 2);
            if (qc == 0) {
                out[ctaBase + wm + mt*16 + g]     = p0 + b4v;
                out[ctaBase + wm + mt*16 + g + 8] = p1 + b4v;
            }
        }
    }
}

extern "C" void kernel_launch(void* const* d_in, const int* in_sizes, int n_in,
                              void* d_out, int out_size) {
    const float* features = (const float*)d_in[0];
    const float* points   = (const float*)d_in[1];
    const float* kmat     = (const float*)d_in[2];
    const float* rtm      = (const float*)d_in[3];
    const float* Bg       = (const float*)d_in[4];
    const float* W1       = (const float*)d_in[5];
    const float* b1       = (const float*)d_in[6];
    const float* W2       = (const float*)d_in[7];
    const float* b2       = (const float*)d_in[8];
    const float* W3       = (const float*)d_in[9];
    const float* b3       = (const float*)d_in[10];
    const float* W4       = (const float*)d_in[11];
    const float* b4       = (const float*)d_in[12];

    transpose_kernel<<<BATCH * (PIX/32), 256>>>(features);
    prep_weights<<<96, 256>>>(W1, W2, W3);
    cudaFuncSetAttribute(prep_frags, cudaFuncAttributeMaxDynamicSharedMemorySize, 52224);
    prep_frags<<<1, 256, 52224>>>();

    cudaFuncSetAttribute(decoder_kernel, cudaFuncAttributeMaxDynamicSharedMemorySize, SMEM_SZ);
    decoder_kernel<<<(BATCH*65536)/256, 256, SMEM_SZ>>>(
        points, kmat, rtm, Bg, b1, b2, b3, W4, b4, (float*)d_out);
}

// round 16
// speedup vs baseline: 5.5402x; 1.0205x over previous
#include <cuda_runtime.h>
#include <cuda_fp16.h>
#include <cstdint>

typedef uint32_t u32;

#define FDIM 128
#define HH 56
#define WW 56
#define BATCH 8
#define PIX (HH*WW)

// ---------------- global scratch ----------------
__device__ float g_feat[BATCH * PIX * FDIM];                 // (b,y,x,c)
__device__ __half g_w1t[64 * 264];                           // W1^T remapped (fp16), stride 264 hw
__device__ __half g_w2t[64 * 72];                            // W2^T, stride 72 hw
__device__ __half g_w3t[64 * 72];
// Pre-built per-lane B fragments (uint4 = 4 regs = 2 n-tiles)
__device__ uint4 g_f1[64][32];                               // [(c*16)+(ks*4)+ntp][lane]
__device__ uint4 g_f2[16][32];                               // [ks*4+ntp][lane]
__device__ uint4 g_f3[16][32];

// ---------------- transpose features ----------------
__global__ __launch_bounds__(256) void transpose_kernel(const float* __restrict__ feat) {
    int blk = blockIdx.x;
    int b = blk / 98;
    int pix0 = (blk % 98) * 32;
    __shared__ float tile[FDIM][33];
    int tx = threadIdx.x & 31;
    int ty = threadIdx.x >> 5;
    const float* src = feat + (size_t)b * FDIM * PIX;
    #pragma unroll
    for (int k = 0; k < 16; k++) {
        int c = ty + (k << 3);
        tile[c][tx] = src[c * PIX + pix0 + tx];
    }
    __syncthreads();
    int c2 = threadIdx.x & 127;
    int pg = threadIdx.x >> 7;
    float* dst = g_feat + ((size_t)b * PIX + pix0) * FDIM;
    #pragma unroll
    for (int p = pg; p < 32; p += 2) {
        dst[p * FDIM + c2] = tile[c2][p];
    }
}

// ---------------- weight prep (fp16) ----------------
__global__ __launch_bounds__(256) void prep_weights(const float* __restrict__ W1,
                                                    const float* __restrict__ W2,
                                                    const float* __restrict__ W3) {
    int t = blockIdx.x * 256 + threadIdx.x;
    if (t < 16384) {                       // W1: [k=256][n=64] -> W1T[n][kk]
        int n = t >> 8, k = t & 255;
        int kk = (k < 128) ? k : (k < 192 ? 128 + 2 * (k - 128) : 129 + 2 * (k - 192));
        g_w1t[n * 264 + kk] = __float2half_rn(W1[k * 64 + n]);
    } else if (t < 16384 + 4096) {
        int i = t - 16384;
        int n = i >> 6, k = i & 63;
        g_w2t[n * 72 + k] = __float2half_rn(W2[k * 64 + n]);
    } else if (t < 16384 + 8192) {
        int i = t - 20480;
        int n = i >> 6, k = i & 63;
        g_w3t[n * 72 + k] = __float2half_rn(W3[k * 64 + n]);
    }
}

// ---------------- helpers ----------------
__device__ __forceinline__ u32 smem_u32(const void* p) {
    u32 a;
    asm("{ .reg .u64 t; cvta.to.shared.u64 t, %1; cvt.u32.u64 %0, t; }" : "=r"(a) : "l"(p));
    return a;
}
__device__ __forceinline__ u32 pack_f16x2(float lo, float hi) {  // low hw = lo
    u32 r; asm("cvt.rn.f16x2.f32 %0, %1, %2;" : "=r"(r) : "f"(hi), "f"(lo)); return r;
}
__device__ __forceinline__ void split2(float v, float& h, float& l) {
    h = __half2float(__float2half_rn(v));
    l = v - h;
}
__device__ __forceinline__ void ldx4(u32* r, u32 addr) {
    asm volatile("ldmatrix.sync.aligned.m8n8.x4.shared.b16 {%0,%1,%2,%3}, [%4];"
        : "=r"(r[0]), "=r"(r[1]), "=r"(r[2]), "=r"(r[3]) : "r"(addr));
}
__device__ __forceinline__ void mma16816(float* d, const u32* a, const u32* b) {
    asm volatile("mma.sync.aligned.m16n8k16.row.col.f32.f16.f16.f32 "
        "{%0,%1,%2,%3}, {%4,%5,%6,%7}, {%8,%9}, {%0,%1,%2,%3};"
        : "+f"(d[0]), "+f"(d[1]), "+f"(d[2]), "+f"(d[3])
        : "r"(a[0]), "r"(a[1]), "r"(a[2]), "r"(a[3]), "r"(b[0]), "r"(b[1]));
}

// ---------------- prep_frags: replay decoder's ldmatrix on staged weights ----------------
// staging smem: W1 @0 (528B rows, 33792B), W2 @33792 (144B rows, 9216B), W3 @43008 (9216B)
__global__ __launch_bounds__(256) void prep_frags() {
    extern __shared__ __align__(16) unsigned char psm[];
    const u32 pb = smem_u32(psm);
    const int tid = threadIdx.x;
    const int warp = tid >> 5;
    const int lane = tid & 31;
    {
        uint4* d4; const uint4* s4;
        d4 = (uint4*)(psm + 0);     s4 = (const uint4*)g_w1t;
        for (int i = tid; i < 2112; i += 256) d4[i] = s4[i];
        d4 = (uint4*)(psm + 33792); s4 = (const uint4*)g_w2t;
        for (int i = tid; i < 576; i += 256) d4[i] = s4[i];
        d4 = (uint4*)(psm + 43008); s4 = (const uint4*)g_w3t;
        for (int i = tid; i < 576; i += 256) d4[i] = s4[i];
    }
    __syncthreads();

    u32 brow = (lane & 7) + ((lane >> 4) << 3);
    u32 khalf = ((lane >> 3) & 1) << 4;
    if (warp < 4) {                       // layer 1, chunk c = warp
        int c = warp;
        for (int ks = 0; ks < 4; ks++) {
            for (int ntp = 0; ntp < 4; ntp++) {
                u32 bk = c*128 + ks*32 + khalf;
                u32 baddr = (ntp*16 + brow) * 528 + bk;
                u32 bh[4];
                ldx4(bh, pb + 0 + baddr);
                g_f1[c*16 + ks*4 + ntp][lane] = make_uint4(bh[0], bh[1], bh[2], bh[3]);
            }
        }
    } else if (warp == 4) {               // layer 2
        for (int ks = 0; ks < 4; ks++) {
            for (int ntp = 0; ntp < 4; ntp++) {
                u32 baddr = (ntp*16 + brow) * 144 + ks*32 + khalf;
                u32 bh[4];
                ldx4(bh, pb + 33792 + baddr);
                g_f2[ks*4 + ntp][lane] = make_uint4(bh[0], bh[1], bh[2], bh[3]);
            }
        }
    } else if (warp == 5) {               // layer 3
        for (int ks = 0; ks < 4; ks++) {
            for (int ntp = 0; ntp < 4; ntp++) {
                u32 baddr = (ntp*16 + brow) * 144 + ks*32 + khalf;
                u32 bh[4];
                ldx4(bh, pb + 43008 + baddr);
                g_f3[ks*4 + ntp][lane] = make_uint4(bh[0], bh[1], bh[2], bh[3]);
            }
        }
    }
}

// ---------------- decoder smem layout (bytes) ----------------
#define S_AH  0                 // 256 rows x 144B
#define S_AL  36864
#define S_B1  73728
#define S_B2  73984
#define S_B3  74240
#define S_W4  74496
#define S_PAR 74752             // 256 points x 32B
#define SMEM_SZ (74752 + 8192)  // 82944

__global__ __launch_bounds__(256, 2) void decoder_kernel(
    const float* __restrict__ points, const float* __restrict__ kmat,
    const float* __restrict__ rtm, const float* __restrict__ Bg,
    const float* __restrict__ b1, const float* __restrict__ b2,
    const float* __restrict__ b3, const float* __restrict__ W4,
    const float* __restrict__ b4, float* __restrict__ out)
{
    extern __shared__ __align__(16) unsigned char sm[];
    const u32 sbase = smem_u32(sm);
    const int tid = threadIdx.x;
    const int warp = tid >> 5;
    const int lane = tid & 31;

    if (tid < 64) {
        ((float*)(sm + S_B1))[tid] = b1[tid];
        ((float*)(sm + S_B2))[tid] = b2[tid];
        ((float*)(sm + S_B3))[tid] = b3[tid];
        ((float*)(sm + S_W4))[tid] = W4[tid];
    }

    // ---- projection: own point -> params table ----
    const int ctaBase = blockIdx.x * 256;
    const int pid = ctaBase + tid;
    const int b = pid >> 16;
    float px = points[pid*3+0], py = points[pid*3+1], pz = points[pid*3+2];
    {
        const float* rtb = rtm + b * 12;
        const float* kb = kmat + b * 9;
        float cx = rtb[0]*px + rtb[1]*py + rtb[2]*pz + rtb[3];
        float cy = rtb[4]*px + rtb[5]*py + rtb[6]*pz + rtb[7];
        float cz = rtb[8]*px + rtb[9]*py + rtb[10]*pz + rtb[11];
        float ix = kb[0]*cx + kb[1]*cy + kb[2]*cz;
        float iy = kb[3]*cx + kb[4]*cy + kb[5]*cz;
        float iz = kb[6]*cx + kb[7]*cy + kb[8]*cz;
        float zd = iz + 1e-8f;
        float u = ix / zd, v = iy / zd;
        float valid = (iz > 0.f) ? 1.f : 0.f;
        float un = (2.f*u + 1.f) / (float)WW - 1.f;
        float vn = (2.f*v + 1.f) / (float)HH - 1.f;
        float xs = ((un + 1.f) * (float)WW - 1.f) * 0.5f;
        float ys = ((vn + 1.f) * (float)HH - 1.f) * 0.5f;
        float x0f = floorf(xs), y0f = floorf(ys);
        float fx = xs - x0f, fy = ys - y0f;
        int x0 = (int)x0f, y0 = (int)y0f, x1 = x0 + 1, y1 = y0 + 1;
        float w00 = (1.f-fx)*(1.f-fy), w01 = fx*(1.f-fy), w10 = (1.f-fx)*fy, w11 = fx*fy;
        w00 *= ((x0>=0 && x0<WW && y0>=0 && y0<HH) ? valid : 0.f);
        w01 *= ((x1>=0 && x1<WW && y0>=0 && y0<HH) ? valid : 0.f);
        w10 *= ((x0>=0 && x0<WW && y1>=0 && y1<HH) ? valid : 0.f);
        w11 *= ((x1>=0 && x1<WW && y1>=0 && y1<HH) ? valid : 0.f);
        int x0c = min(max(x0,0),WW-1), x1c = min(max(x1,0),WW-1);
        int y0c = min(max(y0,0),HH-1), y1c = min(max(y1,0),HH-1);
        int4* pi = (int4*)(sm + S_PAR + tid*32);
        float4* pf = (float4*)(sm + S_PAR + tid*32 + 16);
        *pi = make_int4(((b*HH + y0c)*WW + x0c) * 32, ((b*HH + y0c)*WW + x1c) * 32,
                        ((b*HH + y1c)*WW + x0c) * 32, ((b*HH + y1c)*WW + x1c) * 32);
        *pf = make_float4(w00, w01, w10, w11);
    }
    __syncthreads();   // only CTA barrier

    // ---- layer-1: 4 K-chunks of 64 ----
    const int wm = warp * 32;
    float D[2][8][4];
    #pragma unroll
    for (int mt = 0; mt < 2; mt++)
        #pragma unroll
        for (int nt = 0; nt < 8; nt++)
            #pragma unroll
            for (int q = 0; q < 4; q++) D[mt][nt][q] = 0.f;

    const float4* g4 = (const float4*)g_feat;
    const float TWO_PI = 6.283185307179586f;
    const int half = lane >> 4;
    const int slot = lane & 15;

    #pragma unroll 1
    for (int c = 0; c < 4; c++) {
        if (c < 2) {
            #pragma unroll 2
            for (int pp = 0; pp < 32; pp += 2) {
                int t = wm + pp + half;
                const int4 ci = *(const int4*)(sm + S_PAR + t*32);
                const float4 cw = *(const float4*)(sm + S_PAR + t*32 + 16);
                int c4 = c * 16 + slot;
                float4 A = g4[ci.x + c4];
                float4 B = g4[ci.y + c4];
                float4 C = g4[ci.z + c4];
                float4 E = g4[ci.w + c4];
                float f0 = cw.x*A.x + cw.y*B.x + cw.z*C.x + cw.w*E.x;
                float f1 = cw.x*A.y + cw.y*B.y + cw.z*C.y + cw.w*E.y;
                float f2 = cw.x*A.z + cw.y*B.z + cw.z*C.z + cw.w*E.z;
                float f3 = cw.x*A.w + cw.y*B.w + cw.z*C.w + cw.w*E.w;
                float h0,l0,h1,l1,h2,l2,h3,l3;
                split2(f0,h0,l0); split2(f1,h1,l1); split2(f2,h2,l2); split2(f3,h3,l3);
                u32* dh = (u32*)(sm + S_AH + t*144 + slot*8);
                u32* dl = (u32*)(sm + S_AL + t*144 + slot*8);
                dh[0] = pack_f16x2(h0, h1); dh[1] = pack_f16x2(h2, h3);
                dl[0] = pack_f16x2(l0, l1); dl[1] = pack_f16x2(l2, l3);
            }
        } else {
            int mbase = (c - 2) * 32;
            #pragma unroll
            for (int q = 0; q < 16; q++) {
                int m = mbase + 2 * q;
                float a0 = TWO_PI * (px*__ldg(Bg+3*m)   + py*__ldg(Bg+3*m+1) + pz*__ldg(Bg+3*m+2));
                float a1 = TWO_PI * (px*__ldg(Bg+3*m+3) + py*__ldg(Bg+3*m+4) + pz*__ldg(Bg+3*m+5));
                float s0, cc0, s1, cc1;
                __sincosf(a0, &s0, &cc0);
                __sincosf(a1, &s1, &cc1);
                float h0,l0,h1,l1,h2,l2,h3,l3;
                split2(s0,h0,l0); split2(cc0,h1,l1); split2(s1,h2,l2); split2(cc1,h3,l3);
                u32* dh = (u32*)(sm + S_AH + tid*144 + q*8);
                u32* dl = (u32*)(sm + S_AL + tid*144 + q*8);
                dh[0] = pack_f16x2(h0, h1); dh[1] = pack_f16x2(h2, h3);
                dl[0] = pack_f16x2(l0, l1); dl[1] = pack_f16x2(l2, l3);
            }
        }
        __syncwarp();

        #pragma unroll
        for (int ks = 0; ks < 4; ks++) {
            int k0b = ks * 32;
            u32 ah[2][4], al[2][4];
            u32 arow = wm + (lane & 15);
            u32 akb = k0b + ((lane >> 4) << 4);
            ldx4(ah[0], sbase + S_AH + arow*144 + akb);
            ldx4(al[0], sbase + S_AL + arow*144 + akb);
            ldx4(ah[1], sbase + S_AH + (arow+16)*144 + akb);
            ldx4(al[1], sbase + S_AL + (arow+16)*144 + akb);
            #pragma unroll
            for (int ntp = 0; ntp < 4; ntp++) {
                int idx = c*16 + ks*4 + ntp;
                uint4 vh = g_f1[idx][lane];
                u32 bh[4] = {vh.x, vh.y, vh.z, vh.w};
                int nt = 2 * ntp;
                mma16816(D[0][nt],   ah[0], bh+0);
                mma16816(D[1][nt],   ah[1], bh+0);
                mma16816(D[0][nt],   al[0], bh+0);
                mma16816(D[1][nt],   al[1], bh+0);
                mma16816(D[0][nt+1], ah[0], bh+2);
                mma16816(D[1][nt+1], ah[1], bh+2);
                mma16816(D[0][nt+1], al[0], bh+2);
                mma16816(D[1][nt+1], al[1], bh+2);
            }
        }
        __syncwarp();
    }

    const int g = lane >> 2;
    const int qc = lane & 3;

    // ---- layers 2 and 3: register-resident activations (D fragment == A fragment) ----
    #pragma unroll 1
    for (int layer = 0; layer < 2; layer++) {
        const float* Bv = (const float*)(sm + (layer == 0 ? S_B1 : S_B2));
        #pragma unroll
        for (int mt = 0; mt < 2; mt++) {
            // convert D[mt] -> fp16 hi/lo A fragments, then zero D[mt]
            u32 frh[4][4], frl[4][4];
            #pragma unroll
            for (int ks = 0; ks < 4; ks++) {
                float* d0 = D[mt][2*ks];
                float* d1 = D[mt][2*ks+1];
                int nA = ks*16 + qc*2;
                float bA0 = Bv[nA],   bA1 = Bv[nA+1];
                float bB0 = Bv[nA+8], bB1 = Bv[nA+9];
                float v0 = fmaxf(d0[0] + bA0, 0.f), v1 = fmaxf(d0[1] + bA1, 0.f);
                float v2 = fmaxf(d0[2] + bA0, 0.f), v3 = fmaxf(d0[3] + bA1, 0.f);
                float v4 = fmaxf(d1[0] + bB0, 0.f), v5 = fmaxf(d1[1] + bB1, 0.f);
                float v6 = fmaxf(d1[2] + bB0, 0.f), v7 = fmaxf(d1[3] + bB1, 0.f);
                float h0,l0,h1,l1,h2,l2,h3,l3,h4,l4,h5,l5,h6,l6,h7,l7;
                split2(v0,h0,l0); split2(v1,h1,l1); split2(v2,h2,l2); split2(v3,h3,l3);
                split2(v4,h4,l4); split2(v5,h5,l5); split2(v6,h6,l6); split2(v7,h7,l7);
                frh[ks][0] = pack_f16x2(h0, h1); frl[ks][0] = pack_f16x2(l0, l1);
                frh[ks][1] = pack_f16x2(h2, h3); frl[ks][1] = pack_f16x2(l2, l3);
                frh[ks][2] = pack_f16x2(h4, h5); frl[ks][2] = pack_f16x2(l4, l5);
                frh[ks][3] = pack_f16x2(h6, h7); frl[ks][3] = pack_f16x2(l6, l7);
                d0[0]=0.f; d0[1]=0.f; d0[2]=0.f; d0[3]=0.f;
                d1[0]=0.f; d1[1]=0.f; d1[2]=0.f; d1[3]=0.f;
            }
            #pragma unroll
            for (int ks = 0; ks < 4; ks++) {
                #pragma unroll
                for (int ntp = 0; ntp < 4; ntp++) {
                    int idx = ks*4 + ntp;
                    uint4 vh = layer == 0 ? g_f2[idx][lane] : g_f3[idx][lane];
                    u32 bh[4] = {vh.x, vh.y, vh.z, vh.w};
                    int nt = 2 * ntp;
                    mma16816(D[mt][nt],   frh[ks], bh+0);
                    mma16816(D[mt][nt],   frl[ks], bh+0);
                    mma16816(D[mt][nt+1], frh[ks], bh+2);
                    mma16816(D[mt][nt+1], frl[ks], bh+2);
                }
            }
        }
    }

    // ---- epilogue 3: out = relu(D + b3) . W4 + b4 ----
    {
        const float* B3 = (const float*)(sm + S_B3);
        const float* W4s = (const float*)(sm + S_W4);
        float b4v = b4[0];
        #pragma unroll
        for (int mt = 0; mt < 2; mt++) {
            float p0 = 0.f, p1 = 0.f;
            #pragma unroll
            for (int nt = 0; nt < 8; nt++) {
                int n0 = nt*8 + qc*2;
                p0 += fmaxf(D[mt][nt][0] + B3[n0],   0.f) * W4s[n0];
                p0 += fmaxf(D[mt][nt][1] + B3[n0+1], 0.f) * W4s[n0+1];
                p1 += fmaxf(D[mt][nt][2] + B3[n0],   0.f) * W4s[n0];
                p1 += fmaxf(D[mt][nt][3] + B3[n0+1], 0.f) * W4s[n0+1];
            }
            p0 += __shfl_xor_sync(0xffffffffu, p0, 1);
            p0 += __shfl_xor_sync(0xffffffffu, p0, 2);
            p1 += __shfl_xor_sync(0xffffffffu, p1, 1);
            p1 += __shfl_xor_sync(0xffffffffu, p1, 2);
            if (qc == 0) {
                out[ctaBase + wm + mt*16 + g]     = p0 + b4v;
                out[ctaBase + wm + mt*16 + g + 8] = p1 + b4v;
            }
        }
    }
}

extern "C" void kernel_launch(void* const* d_in, const int* in_sizes, int n_in,
                              void* d_out, int out_size) {
    const float* features = (const float*)d_in[0];
    const float* points   = (const float*)d_in[1];
    const float* kmat     = (const float*)d_in[2];
    const float* rtm      = (const float*)d_in[3];
    const float* Bg       = (const float*)d_in[4];
    const float* W1       = (const float*)d_in[5];
    const float* b1       = (const float*)d_in[6];
    const float* W2       = (const float*)d_in[7];
    const float* b2       = (const float*)d_in[8];
    const float* W3       = (const float*)d_in[9];
    const float* b3       = (const float*)d_in[10];
    const float* W4       = (const float*)d_in[11];
    const float* b4       = (const float*)d_in[12];

    transpose_kernel<<<BATCH * (PIX/32), 256>>>(features);
    prep_weights<<<96, 256>>>(W1, W2, W3);
    cudaFuncSetAttribute(prep_frags, cudaFuncAttributeMaxDynamicSharedMemorySize, 52224);
    prep_frags<<<1, 256, 52224>>>();

    cudaFuncSetAttribute(decoder_kernel, cudaFuncAttributeMaxDynamicSharedMemorySize, SMEM_SZ);
    decoder_kernel<<<(BATCH*65536)/256, 256, SMEM_SZ>>>(
        points, kmat, rtm, Bg, b1, b2, b3, W4, b4, (float*)d_out);
}